// round 10
// baseline (speedup 1.0000x reference)
#include <cuda_runtime.h>
#include <math.h>

// ---------------- problem constants ----------------
#define BATCH 64
#define TDEC  150
#define NVOC  48
#define LHID  256
#define SHID  512
#define NMLP  128

typedef unsigned long long ull;

// ---------------- device scratch ----------------
__device__ float g_xw0[64*1024*1024];
__device__ float g_xw1[64*1024*1024];
__device__ float g_out0[64*1024*512];
__device__ float g_out1[64*512*512];
__device__ float g_feats[64*256*512];
__device__ float g_cf[64*256*128];
__device__ float g_c[2*64*256];
__device__ float g_dh[2*64*512];
__device__ float g_ctx[64*512];
__device__ float g_phiWt[512*128];
__device__ unsigned g_barD;                // decoder barrier

// ---------------- software grid barrier (decoder; R7-proven) ---------------
__device__ __forceinline__ void gbar(unsigned* ctr, unsigned& epoch, unsigned nb)
{
    __syncthreads();
    if (threadIdx.x == 0) {
        unsigned target = epoch + nb;
        asm volatile("red.release.gpu.global.add.u32 [%0], %1;"
                     :: "l"(ctr), "r"(1u) : "memory");
        unsigned v;
        asm volatile("ld.acquire.gpu.global.u32 %0, [%1];"
                     : "=r"(v) : "l"(ctr) : "memory");
        while (v < target) {
            __nanosleep(64);
            asm volatile("ld.acquire.gpu.global.u32 %0, [%1];"
                         : "=r"(v) : "l"(ctr) : "memory");
        }
    }
    epoch += nb;
    __syncthreads();
}

// ---------------- packed fp32x2 FMA (SASS FFMA2) ----------------
__device__ __forceinline__ void fma2(ull& d, ull a, ull b)
{
    asm("fma.rn.f32x2 %0, %1, %2, %0;" : "+l"(d) : "l"(a), "l"(b));
}

union UP { float4 f; ull u[2]; };
union U2 { ull u; float2 f; };

__device__ __forceinline__ unsigned smem_u32(const void* p)
{
    unsigned a;
    asm("{ .reg .u64 t; cvta.to.shared.u64 t, %1; cvt.u32.u64 %0, t; }"
        : "=r"(a) : "l"(p));
    return a;
}

__global__ void reset_bars() { if (threadIdx.x == 0) g_barD = 0; }

// ---------------- fp32 GEMM (R2-proven tile): C = A@W^T + bias -------------
// Tile 128(M) x 64(N), BK=16, 256 threads, 8x4 per thread.
// gate_perm: output column n' maps to weight/bias row (n'&3)*256 + (n'>>2).
__global__ __launch_bounds__(256) void gemm_bias(
    const float* __restrict__ A, const float* __restrict__ W,
    const float* __restrict__ bias, float* __restrict__ C,
    int M, int N, int K, int relu, int gate_perm)
{
    __shared__ float As[16 * 132];
    __shared__ float Ws[16 * 68];
    int bm = blockIdx.y << 7, bn = blockIdx.x << 6;
    int tid = threadIdx.x;
    int ty = tid >> 4, tx = tid & 15;
    const float* Ap = A + (size_t)bm * K;

    int wr = tid >> 2, wc = (tid & 3) << 2;
    int nprime = bn + wr;
    int nrow = gate_perm ? ((nprime & 3) * 256 + (nprime >> 2)) : nprime;
    const float* WpRow = W + (size_t)nrow * K;

    float acc[8][4];
#pragma unroll
    for (int i = 0; i < 8; i++)
#pragma unroll
        for (int j = 0; j < 4; j++) acc[i][j] = 0.f;

    for (int k0 = 0; k0 < K; k0 += 16) {
#pragma unroll
        for (int j = 0; j < 2; j++) {
            int idx = tid + 256 * j;
            int r = idx >> 2, c = (idx & 3) << 2;
            float4 v = *(const float4*)&Ap[(size_t)r * K + k0 + c];
            As[(c + 0) * 132 + r] = v.x;
            As[(c + 1) * 132 + r] = v.y;
            As[(c + 2) * 132 + r] = v.z;
            As[(c + 3) * 132 + r] = v.w;
        }
        {
            float4 v = *(const float4*)&WpRow[k0 + wc];
            Ws[(wc + 0) * 68 + wr] = v.x;
            Ws[(wc + 1) * 68 + wr] = v.y;
            Ws[(wc + 2) * 68 + wr] = v.z;
            Ws[(wc + 3) * 68 + wr] = v.w;
        }
        __syncthreads();
#pragma unroll
        for (int kk = 0; kk < 16; kk++) {
            float4 a0 = *(const float4*)&As[kk * 132 + ty * 8];
            float4 a1 = *(const float4*)&As[kk * 132 + ty * 8 + 4];
            float4 w  = *(const float4*)&Ws[kk * 68 + tx * 4];
            acc[0][0] += a0.x * w.x; acc[0][1] += a0.x * w.y; acc[0][2] += a0.x * w.z; acc[0][3] += a0.x * w.w;
            acc[1][0] += a0.y * w.x; acc[1][1] += a0.y * w.y; acc[1][2] += a0.y * w.z; acc[1][3] += a0.y * w.w;
            acc[2][0] += a0.z * w.x; acc[2][1] += a0.z * w.y; acc[2][2] += a0.z * w.z; acc[2][3] += a0.z * w.w;
            acc[3][0] += a0.w * w.x; acc[3][1] += a0.w * w.y; acc[3][2] += a0.w * w.z; acc[3][3] += a0.w * w.w;
            acc[4][0] += a1.x * w.x; acc[4][1] += a1.x * w.y; acc[4][2] += a1.x * w.z; acc[4][3] += a1.x * w.w;
            acc[5][0] += a1.y * w.x; acc[5][1] += a1.y * w.y; acc[5][2] += a1.y * w.z; acc[5][3] += a1.y * w.w;
            acc[6][0] += a1.z * w.x; acc[6][1] += a1.z * w.y; acc[6][2] += a1.z * w.z; acc[6][3] += a1.z * w.w;
            acc[7][0] += a1.w * w.x; acc[7][1] += a1.w * w.y; acc[7][2] += a1.w * w.z; acc[7][3] += a1.w * w.w;
        }
        __syncthreads();
    }
    float bvx, bvy, bvz, bvw;
    if (gate_perm) {
        int n0 = bn + tx * 4;
        bvx = bias[((n0 + 0) & 3) * 256 + ((n0 + 0) >> 2)];
        bvy = bias[((n0 + 1) & 3) * 256 + ((n0 + 1) >> 2)];
        bvz = bias[((n0 + 2) & 3) * 256 + ((n0 + 2) >> 2)];
        bvw = bias[((n0 + 3) & 3) * 256 + ((n0 + 3) >> 2)];
    } else {
        float4 bv = *(const float4*)&bias[bn + tx * 4];
        bvx = bv.x; bvy = bv.y; bvz = bv.z; bvw = bv.w;
    }
#pragma unroll
    for (int i = 0; i < 8; i++) {
        int m = bm + ty * 8 + i;
        float4 o;
        o.x = acc[i][0] + bvx; o.y = acc[i][1] + bvy;
        o.z = acc[i][2] + bvz; o.w = acc[i][3] + bvw;
        if (relu) {
            o.x = fmaxf(o.x, 0.f); o.y = fmaxf(o.y, 0.f);
            o.z = fmaxf(o.z, 0.f); o.w = fmaxf(o.w, 0.f);
        }
        *(float4*)&C[(size_t)m * N + bn + tx * 4] = o;
    }
}

// ---------------- persistent encoder scan: cluster + DSMEM exchange --------
// grid (8 slices, 8 groups, 2 dirs), cluster (8,1,1) along slices, 512 thr.
// Block (s,g,dir): units [s*32,s*32+32), batches [g*8,g*8+8).
// h lives only in smem: each CTA writes its slice; peers gather via DSMEM.
// warp map: kh = wrp>>3 (k half), ug = wrp&7; lane: bl = lane>>2, ui = lane&3.
// xw is gate-interleaved: xw[(b*Tl+t)*1024 + hu*4 + gate]
#define ENC_SMEM ((128 * 260 + 8 * 260 + 256 * 4 + 2 * 256 + 16) * 4)
__global__ __launch_bounds__(512) __cluster_dims__(8, 1, 1)
void enc_scan(
    const float* __restrict__ xw_f, const float* __restrict__ xw_b,
    const float* __restrict__ whh_f, const float* __restrict__ whh_b,
    float* __restrict__ out, int Tl)
{
    extern __shared__ float smem[];
    float* sh_w  = smem;                  // 128 rows (gate*32+u) x 256 (pitch 260)
    float* sh_x  = smem + 128 * 260;      // 8 rows (batch) x 256 (pitch 260)
    float* sh_p  = sh_x + 8 * 260;        // 256 x 4 partials (kh=1 -> kh=0)
    float* sh_ho = sh_p + 256 * 4;        // [parity][bl][u] = 2 x 8 x 32

    int tid = threadIdx.x;
    int lane = tid & 31, wrp = tid >> 5;
    int kh = wrp >> 3;
    int ug = wrp & 7;
    int bl = lane >> 2;
    int ui = lane & 3;
    int u  = (ug << 2) + ui;          // unit within slice, 0..31
    int s = blockIdx.x, g = blockIdx.y, dir = blockIdx.z;
    int hu = (s << 5) + u;            // global unit 0..255
    int b  = (g << 3) + bl;           // global batch

    const float* xw  = dir ? xw_b  : xw_f;
    const float* Whh = dir ? whh_b : whh_f;

    // resident weights: 128 rows, row r = gate*32 + uu -> Whh[gate*256 + s*32 + uu]
    for (int i = tid; i < 128 * 64; i += 512) {
        int r = i >> 6, kq = (i & 63) << 2;
        int gate = r >> 5, uu = r & 31;
        int grow = (gate << 8) + (s << 5) + uu;
        *(float4*)&sh_w[r * 260 + kq] = *(const float4*)&Whh[(size_t)grow * 256 + kq];
    }
    // h0 = 0
    {
        int bb = tid >> 6, q = tid & 63;
        *(float4*)&sh_x[bb * 260 + q * 4] = make_float4(0.f, 0.f, 0.f, 0.f);
    }
    __syncthreads();

    const unsigned ho_smem = smem_u32(sh_ho);
    const float* wr0 = &sh_w[(0 * 32 + u) * 260 + kh * 128];
    const float* wr1 = &sh_w[(1 * 32 + u) * 260 + kh * 128];
    const float* wr2 = &sh_w[(2 * 32 + u) * 260 + kh * 128];
    const float* wr3 = &sh_w[(3 * 32 + u) * 260 + kh * 128];
    const float* hp  = &sh_x[bl * 260 + kh * 128];
    float* pp = &sh_p[((ug << 5) + lane) * 4];
    float creg = 0.f;

    // first-step gate prefetch
    float4 xg = make_float4(0.f, 0.f, 0.f, 0.f);
    if (kh == 0) {
        int tt0 = dir ? (Tl - 1) : 0;
        xg = __ldg((const float4*)&xw[((size_t)b * Tl + tt0) * 1024 + (hu << 2)]);
    }

    for (int t = 0; t < Tl; t++) {
        int tt = dir ? (Tl - 1 - t) : t;

        ull A0 = 0ull, A1 = 0ull, A2 = 0ull, A3 = 0ull;
#pragma unroll 8
        for (int kk = 0; kk < 128; kk += 4) {
            UP h, w0, w1, w2, w3;
            h.f  = *(const float4*)&hp[kk];
            w0.f = *(const float4*)&wr0[kk];
            w1.f = *(const float4*)&wr1[kk];
            w2.f = *(const float4*)&wr2[kk];
            w3.f = *(const float4*)&wr3[kk];
            fma2(A0, h.u[0], w0.u[0]); fma2(A1, h.u[0], w1.u[0]);
            fma2(A2, h.u[0], w2.u[0]); fma2(A3, h.u[0], w3.u[0]);
            fma2(A0, h.u[1], w0.u[1]); fma2(A1, h.u[1], w1.u[1]);
            fma2(A2, h.u[1], w2.u[1]); fma2(A3, h.u[1], w3.u[1]);
        }
        U2 r0, r1, r2, r3;
        r0.u = A0; r1.u = A1; r2.u = A2; r3.u = A3;
        if (kh == 1) {
            *(float4*)pp = make_float4(r0.f.x + r0.f.y, r1.f.x + r1.f.y,
                                       r2.f.x + r2.f.y, r3.f.x + r3.f.y);
        }
        __syncthreads();

        float hn = 0.f;
        if (kh == 0) {
            float4 p = *(const float4*)pp;
            float zi = r0.f.x + r0.f.y + p.x + xg.x;
            float zf = r1.f.x + r1.f.y + p.y + xg.y;
            float zg = r2.f.x + r2.f.y + p.z + xg.z;
            float zo = r3.f.x + r3.f.y + p.w + xg.w;
            float si = 1.f / (1.f + expf(-zi));
            float sf = 1.f / (1.f + expf(-zf));
            float so = 1.f / (1.f + expf(-zo));
            float cn = sf * creg + si * tanhf(zg);
            hn = so * tanhf(cn);
            creg = cn;
            sh_ho[(t & 1) * 256 + bl * 32 + u] = hn;   // own-slice publish
        }

        // cluster arrive (releases smem slice); hide global ops; wait
        asm volatile("barrier.cluster.arrive.aligned;" ::: "memory");
        if (kh == 0) {
            out[((size_t)b * Tl + tt) * 512 + dir * 256 + hu] = hn;
            if (t + 1 < Tl) {
                int tn = dir ? (Tl - 2 - t) : (t + 1);
                xg = __ldg((const float4*)&xw[((size_t)b * Tl + tn) * 1024 + (hu << 2)]);
            }
        }
        asm volatile("barrier.cluster.wait.aligned;" ::: "memory");

        // gather full h (8 x 256) from the 8 cluster CTAs via DSMEM
        {
            int bb = tid >> 6, q = tid & 63;
            unsigned lbase = ho_smem + (((t & 1) * 256) + bb * 32 + (q & 7) * 4) * 4;
            unsigned raddr;
            asm("mapa.shared::cluster.u32 %0, %1, %2;"
                : "=r"(raddr) : "r"(lbase), "r"(q >> 3));
            float4 v;
            asm volatile("ld.shared::cluster.v4.f32 {%0,%1,%2,%3}, [%4];"
                         : "=f"(v.x), "=f"(v.y), "=f"(v.z), "=f"(v.w) : "r"(raddr));
            *(float4*)&sh_x[bb * 260 + q * 4] = v;
        }
        __syncthreads();
    }
    if (kh == 0)
        g_c[(size_t)(dir * 64 + b) * 256 + hu] = creg;
}

// ---------------- persistent decoder (R8-proven) ----------------
#define DEC_SMEM ((16 * 1032 + 64 * 132 + 512 + 128 + 256 + 512 + 64 + 256) * 4)
__global__ __launch_bounds__(256) void dec_scan(
    const float* __restrict__ sWih, const float* __restrict__ sWhh,
    const float* __restrict__ sb, const int* __restrict__ gt,
    const float* __restrict__ phi_b,
    const float* __restrict__ fcW, const float* __restrict__ fcb,
    float* __restrict__ out_lps)
{
    extern __shared__ float smem[];
    float* sh_w  = smem;
    float* sh_x  = sh_w + 16 * 1032;
    float* sh_h  = sh_x + 64 * 132;
    float* sh_q  = sh_h + 512;
    float* sh_e  = sh_q + 128;
    float* sh_c2 = sh_e + 256;
    float* sh_l  = sh_c2 + 512;
    float* sr    = sh_l + 64;

    int tid = threadIdx.x;
    int lane = tid & 31, wrp = tid >> 5;
    int u = wrp & 3, bh = wrp >> 2;
    int b = bh * 32 + lane;
    int hu0 = blockIdx.x << 2;
    int hu = hu0 + u;
    unsigned epoch = 0;
    const unsigned nb = gridDim.x;
    unsigned* ctr = &g_barD;

    for (int i = tid; i < 16 * 256; i += 256) {
        int r = i >> 8, kq = (i & 255) << 2;
        int grow = (r >> 2) * SHID + hu0 + (r & 3);
        float4 v;
        if (kq < 512) v = *(const float4*)&sWih[(size_t)grow * 560 + 48 + kq];
        else          v = *(const float4*)&sWhh[(size_t)grow * 512 + (kq - 512)];
        *(float4*)&sh_w[r * 1032 + kq] = v;
    }

    float creg = 0.f;
    __stcg(&g_dh[(size_t)b * 512 + hu], 0.f);
    __stcg(&g_ctx[(size_t)b * 512 + hu], __ldg(&g_feats[(size_t)b * 256 * 512 + hu]));
    gbar(ctr, epoch, nb);

    float bi0 = sb[0 * SHID + hu], bi1 = sb[1 * SHID + hu];
    float bi2 = sb[2 * SHID + hu], bi3 = sb[3 * SHID + hu];

    for (int t = 0; t < TDEC; t++) {
        int pin = t & 1, pout = pin ^ 1;
        int tok = (t == 0) ? 0 : gt[b * TDEC + (t - 1)];
        U2 A0, A1, A2, A3;
        A0.f = make_float2(sWih[(size_t)(0 * SHID + hu) * 560 + tok] + bi0, 0.f);
        A1.f = make_float2(sWih[(size_t)(1 * SHID + hu) * 560 + tok] + bi1, 0.f);
        A2.f = make_float2(sWih[(size_t)(2 * SHID + hu) * 560 + tok] + bi2, 0.f);
        A3.f = make_float2(sWih[(size_t)(3 * SHID + hu) * 560 + tok] + bi3, 0.f);

        const float* hin = g_dh + (size_t)pin * 64 * 512;
        for (int c = 0; c < 8; c++) {
            __syncthreads();
            const float* src = (c < 4) ? (g_ctx + (c << 7)) : (hin + ((c - 4) << 7));
            for (int i = tid; i < 64 * 32; i += 256) {
                int bb = i >> 5, kq = (i & 31) << 2;
                *(float4*)&sh_x[bb * 132 + kq] = __ldcg((const float4*)&src[(size_t)bb * 512 + kq]);
            }
            __syncthreads();
            const float* wp = sh_w + c * 128;
#pragma unroll 8
            for (int kk = 0; kk < 128; kk += 4) {
                UP h, w0, w1, w2, w3;
                h.f  = *(const float4*)&sh_x[b * 132 + kk];
                w0.f = *(const float4*)&wp[(0 * 4 + u) * 1032 + kk];
                w1.f = *(const float4*)&wp[(1 * 4 + u) * 1032 + kk];
                w2.f = *(const float4*)&wp[(2 * 4 + u) * 1032 + kk];
                w3.f = *(const float4*)&wp[(3 * 4 + u) * 1032 + kk];
                fma2(A0.u, h.u[0], w0.u[0]); fma2(A1.u, h.u[0], w1.u[0]);
                fma2(A2.u, h.u[0], w2.u[0]); fma2(A3.u, h.u[0], w3.u[0]);
                fma2(A0.u, h.u[1], w0.u[1]); fma2(A1.u, h.u[1], w1.u[1]);
                fma2(A2.u, h.u[1], w2.u[1]); fma2(A3.u, h.u[1], w3.u[1]);
            }
        }
        float acc0 = A0.f.x + A0.f.y;
        float acc1 = A1.f.x + A1.f.y;
        float acc2 = A2.f.x + A2.f.y;
        float acc3 = A3.f.x + A3.f.y;
        float si = 1.f / (1.f + expf(-acc0));
        float sf = 1.f / (1.f + expf(-acc1));
        float so = 1.f / (1.f + expf(-acc3));
        float cn = sf * creg + si * tanhf(acc2);
        float hn = so * tanhf(cn);
        creg = cn;
        __stcg(&g_dh[(size_t)pout * 64 * 512 + b * 512 + hu], hn);
        gbar(ctr, epoch, nb);

        if (blockIdx.x < 64) {
            int bb = blockIdx.x;
            const float* h = g_dh + (size_t)pout * 64 * 512 + (size_t)bb * 512;
            for (int i = tid; i < 512; i += 256) sh_h[i] = __ldcg(&h[i]);
            __syncthreads();

            {
                int j = tid >> 1, hf = tid & 1;
                const float* pw = g_phiWt + (size_t)hf * 256 * 128;
                const float* hh = sh_h + hf * 256;
                float a0 = 0.f, a1 = 0.f, a2 = 0.f, a3 = 0.f;
                for (int k = 0; k < 256; k += 4) {
                    a0 += hh[k + 0] * pw[(k + 0) * 128 + j];
                    a1 += hh[k + 1] * pw[(k + 1) * 128 + j];
                    a2 += hh[k + 2] * pw[(k + 2) * 128 + j];
                    a3 += hh[k + 3] * pw[(k + 3) * 128 + j];
                }
                sr[tid] = a0 + a1 + a2 + a3;
            }
            __syncthreads();
            if (tid < 128) {
                float q = sr[2 * tid] + sr[2 * tid + 1] + phi_b[tid];
                sh_q[tid] = q > 0.f ? q : 0.f;
            }
            __syncthreads();

            {
                const float* cfp = g_cf + ((size_t)bb * 256 + tid) * 128;
                float a0 = 0.f, a1 = 0.f, a2 = 0.f, a3 = 0.f;
                for (int j = 0; j < 128; j += 4) {
                    a0 += sh_q[j + 0] * cfp[j + 0];
                    a1 += sh_q[j + 1] * cfp[j + 1];
                    a2 += sh_q[j + 2] * cfp[j + 2];
                    a3 += sh_q[j + 3] * cfp[j + 3];
                }
                sh_e[tid] = a0 + a1 + a2 + a3;
            }
            __syncthreads();

            float v = sh_e[tid];
            sr[tid] = v; __syncthreads();
            for (int s = 128; s > 0; s >>= 1) { if (tid < s) sr[tid] = fmaxf(sr[tid], sr[tid + s]); __syncthreads(); }
            float m = sr[0]; __syncthreads();
            float e = expf(v - m);
            sr[tid] = e; __syncthreads();
            for (int s = 128; s > 0; s >>= 1) { if (tid < s) sr[tid] += sr[tid + s]; __syncthreads(); }
            float inv = 1.f / sr[0];
            __syncthreads();
            sh_e[tid] = e * inv;
            __syncthreads();

            for (int d0 = 0; d0 < 512; d0 += 256) {
                int d = d0 + tid;
                const float* fp = g_feats + (size_t)bb * 256 * 512 + d;
                float a0 = 0.f, a1 = 0.f, a2 = 0.f, a3 = 0.f;
                for (int tt2 = 0; tt2 < 256; tt2 += 4) {
                    a0 += sh_e[tt2 + 0] * fp[(size_t)(tt2 + 0) * 512];
                    a1 += sh_e[tt2 + 1] * fp[(size_t)(tt2 + 1) * 512];
                    a2 += sh_e[tt2 + 2] * fp[(size_t)(tt2 + 2) * 512];
                    a3 += sh_e[tt2 + 3] * fp[(size_t)(tt2 + 3) * 512];
                }
                float cv = a0 + a1 + a2 + a3;
                sh_c2[d] = cv;
                __stcg(&g_ctx[(size_t)bb * 512 + d], cv);
            }
            __syncthreads();

            if (tid < 192) {
                int v2 = tid >> 2, part = tid & 3;
                const float* wr = fcW + (size_t)v2 * 1024 + part * 256;
                const float* src = (part < 2) ? (sh_h + part * 256) : (sh_c2 + (part - 2) * 256);
                float a0 = 0.f, a1 = 0.f, a2 = 0.f, a3 = 0.f;
                for (int k = 0; k < 256; k += 4) {
                    a0 += src[k + 0] * wr[k + 0];
                    a1 += src[k + 1] * wr[k + 1];
                    a2 += src[k + 2] * wr[k + 2];
                    a3 += src[k + 3] * wr[k + 3];
                }
                sr[tid] = a0 + a1 + a2 + a3;
            }
            __syncthreads();
            if (tid < 48) {
                sh_l[tid] = sr[tid * 4] + sr[tid * 4 + 1] + sr[tid * 4 + 2] + sr[tid * 4 + 3] + fcb[tid];
            }
            __syncthreads();
            if (tid < 48) {
                float m2 = -1e30f;
                for (int j = 0; j < 48; j++) m2 = fmaxf(m2, sh_l[j]);
                float s2 = 0.f;
                for (int j = 0; j < 48; j++) s2 += expf(sh_l[j] - m2);
                out_lps[(size_t)bb * TDEC * NVOC + (size_t)t * NVOC + tid] = sh_l[tid] - m2 - logf(s2);
            }
        }
        gbar(ctr, epoch, nb);
    }
}

// ---------------- small helpers ----------------
__global__ void transpose_phi(const float* __restrict__ W) {
    int j = blockIdx.x;
    for (int k = threadIdx.x; k < 512; k += 256) g_phiWt[k * 128 + j] = W[j * 512 + k];
}

// listener_hc: h_fwd = feats[b, 255, 0:256], h_bwd = feats[b, 0, 256:512]
__global__ void fin_hc(float* __restrict__ out) {
    int b = blockIdx.x;
    for (int i = threadIdx.x; i < 1024; i += 256) {
        int q = i >> 8, r = i & 255;
        float v;
        if (q == 0)      v = g_feats[((size_t)b * 256 + 255) * 512 + r];
        else if (q == 1) v = g_feats[((size_t)b * 256 + 0) * 512 + 256 + r];
        else if (q == 2) v = g_c[(size_t)(0 * 64 + b) * 256 + r];
        else             v = g_c[(size_t)(1 * 64 + b) * 256 + r];
        out[(size_t)b * 1024 + i] = v;
    }
}

// ---------------- host launcher ----------------
extern "C" void kernel_launch(void* const* d_in, const int* in_sizes, int n_in,
                              void* d_out, int out_size)
{
    const float* inputs = (const float*)d_in[0];
    const int*   gt     = (const int*)d_in[1];
    const float* W[27];
    for (int i = 0; i < 27; i++) W[i] = (const float*)d_in[i + 2];

    float *xw0, *xw1, *out0, *out1, *feats, *cf;
    cudaGetSymbolAddress((void**)&xw0, g_xw0);
    cudaGetSymbolAddress((void**)&xw1, g_xw1);
    cudaGetSymbolAddress((void**)&out0, g_out0);
    cudaGetSymbolAddress((void**)&out1, g_out1);
    cudaGetSymbolAddress((void**)&feats, g_feats);
    cudaGetSymbolAddress((void**)&cf, g_cf);

    cudaFuncSetAttribute(enc_scan, cudaFuncAttributeMaxDynamicSharedMemorySize, ENC_SMEM);
    cudaFuncSetAttribute(dec_scan, cudaFuncAttributeMaxDynamicSharedMemorySize, DEC_SMEM);

    float* dout = (float*)d_out;

    reset_bars<<<1, 32>>>();   // launch #0

    // ---------------- encoder ----------------
    const float* A = inputs;
    float* outs[3] = {out0, out1, feats};
    int Tl = 1024, K = 160;
    for (int l = 0; l < 3; l++) {
        int M = 64 * Tl;
        dim3 gg(1024 / 64, M / 128);
        gemm_bias<<<gg, 256>>>(A, W[l * 6 + 0], W[l * 6 + 2], xw0, M, 1024, K, 0, 1);
        gemm_bias<<<gg, 256>>>(A, W[l * 6 + 3], W[l * 6 + 5], xw1, M, 1024, K, 0, 1);
        enc_scan<<<dim3(8, 8, 2), 512, ENC_SMEM>>>(xw0, xw1, W[l * 6 + 1], W[l * 6 + 4],
                                                   outs[l], Tl);
        A = outs[l];
        Tl >>= 1;
        K = 1024;
    }

    // comp_feat = relu(feats @ psi_W^T + psi_b)   [16384,128]
    gemm_bias<<<dim3(2, 16384 / 128), 256>>>(feats, W[23], W[24], cf, 16384, 128, 512, 1, 0);
    transpose_phi<<<128, 256>>>(W[21]);
    fin_hc<<<64, 256>>>(dout + (size_t)BATCH * TDEC * NVOC);

    // ---------------- decoder ----------------
    dec_scan<<<128, 256, DEC_SMEM>>>(W[18], W[19], W[20], gt, W[22], W[25], W[26], dout);
}

// round 12
// speedup vs baseline: 1.0111x; 1.0111x over previous
#include <cuda_runtime.h>
#include <math.h>

// ---------------- problem constants ----------------
#define BATCH 64
#define TDEC  150
#define NVOC  48
#define LHID  256
#define SHID  512
#define NMLP  128

typedef unsigned long long ull;

// ---------------- device scratch ----------------
__device__ float g_xw0[64*1024*1024];
__device__ float g_xw1[64*1024*1024];
__device__ float g_out0[64*1024*512];
__device__ float g_out1[64*512*512];
__device__ float g_feats[64*256*512];
__device__ float g_cf[64*256*128];
__device__ float g_h[2*2*64*256];          // [parity][dir][b][256]
__device__ float g_c[2*64*256];
__device__ float g_dh[2*64*512];
__device__ float g_ctx[64*512];
__device__ float g_phiWt[512*128];
__device__ unsigned g_barE[2];             // per-direction encoder barriers
__device__ unsigned g_barD;                // decoder barrier

// ---------------- split-phase grid barrier (R7/R8-PROVEN primitives) -------
__device__ __forceinline__ void gbar_arrive(unsigned* ctr)
{
    __syncthreads();
    if (threadIdx.x == 0) {
        asm volatile("red.release.gpu.global.add.u32 [%0], %1;"
                     :: "l"(ctr), "r"(1u) : "memory");
    }
}
__device__ __forceinline__ void gbar_wait(unsigned* ctr, unsigned& epoch, unsigned nb)
{
    if (threadIdx.x == 0) {
        unsigned target = epoch + nb;
        unsigned v;
        asm volatile("ld.acquire.gpu.global.u32 %0, [%1];"
                     : "=r"(v) : "l"(ctr) : "memory");
        while (v < target) {
            __nanosleep(64);
            asm volatile("ld.acquire.gpu.global.u32 %0, [%1];"
                         : "=r"(v) : "l"(ctr) : "memory");
        }
    }
    epoch += nb;
    __syncthreads();
}
__device__ __forceinline__ void gbar(unsigned* ctr, unsigned& epoch, unsigned nb)
{
    gbar_arrive(ctr);
    gbar_wait(ctr, epoch, nb);
}

// ---------------- packed fp32x2 FMA (SASS FFMA2) ----------------
__device__ __forceinline__ void fma2(ull& d, ull a, ull b)
{
    asm("fma.rn.f32x2 %0, %1, %2, %0;" : "+l"(d) : "l"(a), "l"(b));
}

union UP { float4 f; ull u[2]; };
union U2 { ull u; float2 f; };

// ---------------- barrier reset + pad launches ----------------
__global__ void reset_bars() {
    if (threadIdx.x == 0 && blockIdx.x == 0) {
        g_barE[0] = 0; g_barE[1] = 0; g_barD = 0;
    }
}
__global__ void nop_kernel() {}

// ---------------- fp32 GEMM (R2-proven tile): C = A@W^T + bias -------------
// Tile 128(M) x 64(N), BK=16, 256 threads, 8x4 per thread.
// gate_perm: output column n' maps to weight/bias row (n'&3)*256 + (n'>>2).
__global__ __launch_bounds__(256) void gemm_bias(
    const float* __restrict__ A, const float* __restrict__ W,
    const float* __restrict__ bias, float* __restrict__ C,
    int M, int N, int K, int relu, int gate_perm)
{
    __shared__ float As[16 * 132];
    __shared__ float Ws[16 * 68];
    int bm = blockIdx.y << 7, bn = blockIdx.x << 6;
    int tid = threadIdx.x;
    int ty = tid >> 4, tx = tid & 15;
    const float* Ap = A + (size_t)bm * K;

    int wr = tid >> 2, wc = (tid & 3) << 2;
    int nprime = bn + wr;
    int nrow = gate_perm ? ((nprime & 3) * 256 + (nprime >> 2)) : nprime;
    const float* WpRow = W + (size_t)nrow * K;

    float acc[8][4];
#pragma unroll
    for (int i = 0; i < 8; i++)
#pragma unroll
        for (int j = 0; j < 4; j++) acc[i][j] = 0.f;

    for (int k0 = 0; k0 < K; k0 += 16) {
#pragma unroll
        for (int j = 0; j < 2; j++) {
            int idx = tid + 256 * j;
            int r = idx >> 2, c = (idx & 3) << 2;
            float4 v = *(const float4*)&Ap[(size_t)r * K + k0 + c];
            As[(c + 0) * 132 + r] = v.x;
            As[(c + 1) * 132 + r] = v.y;
            As[(c + 2) * 132 + r] = v.z;
            As[(c + 3) * 132 + r] = v.w;
        }
        {
            float4 v = *(const float4*)&WpRow[k0 + wc];
            Ws[(wc + 0) * 68 + wr] = v.x;
            Ws[(wc + 1) * 68 + wr] = v.y;
            Ws[(wc + 2) * 68 + wr] = v.z;
            Ws[(wc + 3) * 68 + wr] = v.w;
        }
        __syncthreads();
#pragma unroll
        for (int kk = 0; kk < 16; kk++) {
            float4 a0 = *(const float4*)&As[kk * 132 + ty * 8];
            float4 a1 = *(const float4*)&As[kk * 132 + ty * 8 + 4];
            float4 w  = *(const float4*)&Ws[kk * 68 + tx * 4];
            acc[0][0] += a0.x * w.x; acc[0][1] += a0.x * w.y; acc[0][2] += a0.x * w.z; acc[0][3] += a0.x * w.w;
            acc[1][0] += a0.y * w.x; acc[1][1] += a0.y * w.y; acc[1][2] += a0.y * w.z; acc[1][3] += a0.y * w.w;
            acc[2][0] += a0.z * w.x; acc[2][1] += a0.z * w.y; acc[2][2] += a0.z * w.z; acc[2][3] += a0.z * w.w;
            acc[3][0] += a0.w * w.x; acc[3][1] += a0.w * w.y; acc[3][2] += a0.w * w.z; acc[3][3] += a0.w * w.w;
            acc[4][0] += a1.x * w.x; acc[4][1] += a1.x * w.y; acc[4][2] += a1.x * w.z; acc[4][3] += a1.x * w.w;
            acc[5][0] += a1.y * w.x; acc[5][1] += a1.y * w.y; acc[5][2] += a1.y * w.z; acc[5][3] += a1.y * w.w;
            acc[6][0] += a1.z * w.x; acc[6][1] += a1.z * w.y; acc[6][2] += a1.z * w.z; acc[6][3] += a1.z * w.w;
            acc[7][0] += a1.w * w.x; acc[7][1] += a1.w * w.y; acc[7][2] += a1.w * w.z; acc[7][3] += a1.w * w.w;
        }
        __syncthreads();
    }
    float bvx, bvy, bvz, bvw;
    if (gate_perm) {
        int n0 = bn + tx * 4;
        bvx = bias[((n0 + 0) & 3) * 256 + ((n0 + 0) >> 2)];
        bvy = bias[((n0 + 1) & 3) * 256 + ((n0 + 1) >> 2)];
        bvz = bias[((n0 + 2) & 3) * 256 + ((n0 + 2) >> 2)];
        bvw = bias[((n0 + 3) & 3) * 256 + ((n0 + 3) >> 2)];
    } else {
        float4 bv = *(const float4*)&bias[bn + tx * 4];
        bvx = bv.x; bvy = bv.y; bvz = bv.z; bvw = bv.w;
    }
#pragma unroll
    for (int i = 0; i < 8; i++) {
        int m = bm + ty * 8 + i;
        float4 o;
        o.x = acc[i][0] + bvx; o.y = acc[i][1] + bvy;
        o.z = acc[i][2] + bvz; o.w = acc[i][3] + bvw;
        if (relu) {
            o.x = fmaxf(o.x, 0.f); o.y = fmaxf(o.y, 0.f);
            o.z = fmaxf(o.z, 0.f); o.w = fmaxf(o.w, 0.f);
        }
        *(float4*)&C[(size_t)m * N + bn + tx * 4] = o;
    }
}

// ---------------- persistent encoder scan: BOTH dirs per block -------------
// 64 blocks x 512 threads. Each block owns unit slice [hu0,hu0+4) for fwd AND
// bwd chains; the two chains' barrier latencies hide behind each other.
// warp map (per phase): kh = wrp>>3, u = (wrp>>1)&3, bh = wrp&1.
// xw is gate-interleaved: xw[(b*Tl+t)*1024 + hu*4 + gate]
#define ENC_SMEM ((2 * 16 * 264 + 64 * 260 + 256 * 4) * 4)
__global__ __launch_bounds__(512) void enc_scan(
    const float* __restrict__ xw_f, const float* __restrict__ xw_b,
    const float* __restrict__ whh_f, const float* __restrict__ whh_b,
    float* __restrict__ out, int Tl, unsigned epoch0)
{
    extern __shared__ float smem[];
    float* sh_w = smem;                    // [dir][16 x 256 (pitch 264)]
    float* sh_x = smem + 2 * 16 * 264;     // 64 x 256 (pitch 260)
    float* sh_p = sh_x + 64 * 260;         // 256 x 4 partials

    int tid = threadIdx.x;
    int lane = tid & 31, wrp = tid >> 5;
    int kh = wrp >> 3;
    int u = (wrp >> 1) & 3;
    int bh = wrp & 1;
    int b = bh * 32 + lane;
    int hu0 = blockIdx.x << 2;
    int hu = hu0 + u;
    unsigned epochF = epoch0, epochB = epoch0;
    const unsigned nb = gridDim.x;         // 64 blocks per chain
    unsigned* ctrF = &g_barE[0];
    unsigned* ctrB = &g_barE[1];

    // resident weights for both dirs: rows r = gate*4 + unit
    for (int i = tid; i < 2 * 16 * 64; i += 512) {
        int r32 = i >> 6, kq = (i & 63) << 2;
        int dw = r32 >> 4, r = r32 & 15;
        int grow = ((r >> 2) << 8) + hu0 + (r & 3);
        const float* Whh = dw ? whh_b : whh_f;
        *(float4*)&sh_w[(size_t)dw * 16 * 264 + r * 264 + kq] =
            *(const float4*)&Whh[(size_t)grow * 256 + kq];
    }

    float cregF = 0.f, cregB = 0.f;
    if (kh == 0) {
        __stcg(&g_h[(size_t)(0 * 2 + 0) * 64 * 256 + b * 256 + hu], 0.f);
        __stcg(&g_h[(size_t)(0 * 2 + 1) * 64 * 256 + b * 256 + hu], 0.f);
    }
    gbar(ctrF, epochF, nb);
    gbar(ctrB, epochB, nb);

    const float* wF0 = &sh_w[0 * 16 * 264 + (0 * 4 + u) * 264 + kh * 128];
    const float* wF1 = &sh_w[0 * 16 * 264 + (1 * 4 + u) * 264 + kh * 128];
    const float* wF2 = &sh_w[0 * 16 * 264 + (2 * 4 + u) * 264 + kh * 128];
    const float* wF3 = &sh_w[0 * 16 * 264 + (3 * 4 + u) * 264 + kh * 128];
    const float* wB0 = &sh_w[1 * 16 * 264 + (0 * 4 + u) * 264 + kh * 128];
    const float* wB1 = &sh_w[1 * 16 * 264 + (1 * 4 + u) * 264 + kh * 128];
    const float* wB2 = &sh_w[1 * 16 * 264 + (2 * 4 + u) * 264 + kh * 128];
    const float* wB3 = &sh_w[1 * 16 * 264 + (3 * 4 + u) * 264 + kh * 128];
    const float* hp  = &sh_x[b * 260 + kh * 128];
    float* pp = &sh_p[(u * 64 + b) * 4];

    // first-step gate prefetch (both chains)
    float4 xgF = make_float4(0.f, 0.f, 0.f, 0.f);
    float4 xgB = make_float4(0.f, 0.f, 0.f, 0.f);
    if (kh == 0) {
        xgF = __ldg((const float4*)&xw_f[((size_t)b * Tl + 0) * 1024 + (hu << 2)]);
        xgB = __ldg((const float4*)&xw_b[((size_t)b * Tl + (Tl - 1)) * 1024 + (hu << 2)]);
    }

    for (int t = 0; t < Tl; t++) {
        int pin = t & 1, pout = pin ^ 1;

        // ================= FWD phase =================
        if (t > 0) gbar_wait(ctrF, epochF, nb);
        {
            const float* hin = g_h + (size_t)(pin * 2 + 0) * 64 * 256;
            for (int i = tid; i < 4096; i += 512) {
                int bb = i >> 6, kq = (i & 63) << 2;
                *(float4*)&sh_x[bb * 260 + kq] = __ldcg((const float4*)&hin[bb * 256 + kq]);
            }
            __syncthreads();

            ull A0 = 0ull, A1 = 0ull, A2 = 0ull, A3 = 0ull;
#pragma unroll 8
            for (int kk = 0; kk < 128; kk += 4) {
                UP h, w0, w1, w2, w3;
                h.f  = *(const float4*)&hp[kk];
                w0.f = *(const float4*)&wF0[kk];
                w1.f = *(const float4*)&wF1[kk];
                w2.f = *(const float4*)&wF2[kk];
                w3.f = *(const float4*)&wF3[kk];
                fma2(A0, h.u[0], w0.u[0]); fma2(A1, h.u[0], w1.u[0]);
                fma2(A2, h.u[0], w2.u[0]); fma2(A3, h.u[0], w3.u[0]);
                fma2(A0, h.u[1], w0.u[1]); fma2(A1, h.u[1], w1.u[1]);
                fma2(A2, h.u[1], w2.u[1]); fma2(A3, h.u[1], w3.u[1]);
            }
            U2 r0, r1, r2, r3;
            r0.u = A0; r1.u = A1; r2.u = A2; r3.u = A3;
            if (kh == 1) {
                *(float4*)pp = make_float4(r0.f.x + r0.f.y, r1.f.x + r1.f.y,
                                           r2.f.x + r2.f.y, r3.f.x + r3.f.y);
            }
            __syncthreads();

            float hn = 0.f;
            if (kh == 0) {
                float4 p = *(const float4*)pp;
                float zi = r0.f.x + r0.f.y + p.x + xgF.x;
                float zf = r1.f.x + r1.f.y + p.y + xgF.y;
                float zg = r2.f.x + r2.f.y + p.z + xgF.z;
                float zo = r3.f.x + r3.f.y + p.w + xgF.w;
                float si = 1.f / (1.f + expf(-zi));
                float sf = 1.f / (1.f + expf(-zf));
                float so = 1.f / (1.f + expf(-zo));
                float cn = sf * cregF + si * tanhf(zg);
                hn = so * tanhf(cn);
                cregF = cn;
                __stcg(&g_h[(size_t)(pout * 2 + 0) * 64 * 256 + b * 256 + hu], hn);
            }
            gbar_arrive(ctrF);
            if (kh == 0) {
                out[((size_t)b * Tl + t) * 512 + hu] = hn;
                if (t + 1 < Tl)
                    xgF = __ldg((const float4*)&xw_f[((size_t)b * Tl + t + 1) * 1024 + (hu << 2)]);
            }
        }

        // ================= BWD phase =================
        if (t > 0) gbar_wait(ctrB, epochB, nb);
        else       __syncthreads();   // protect sh_x overwrite at t=0 (arrive already synced; keep explicit)
        {
            int tt = Tl - 1 - t;
            const float* hin = g_h + (size_t)(pin * 2 + 1) * 64 * 256;
            for (int i = tid; i < 4096; i += 512) {
                int bb = i >> 6, kq = (i & 63) << 2;
                *(float4*)&sh_x[bb * 260 + kq] = __ldcg((const float4*)&hin[bb * 256 + kq]);
            }
            __syncthreads();

            ull A0 = 0ull, A1 = 0ull, A2 = 0ull, A3 = 0ull;
#pragma unroll 8
            for (int kk = 0; kk < 128; kk += 4) {
                UP h, w0, w1, w2, w3;
                h.f  = *(const float4*)&hp[kk];
                w0.f = *(const float4*)&wB0[kk];
                w1.f = *(const float4*)&wB1[kk];
                w2.f = *(const float4*)&wB2[kk];
                w3.f = *(const float4*)&wB3[kk];
                fma2(A0, h.u[0], w0.u[0]); fma2(A1, h.u[0], w1.u[0]);
                fma2(A2, h.u[0], w2.u[0]); fma2(A3, h.u[0], w3.u[0]);
                fma2(A0, h.u[1], w0.u[1]); fma2(A1, h.u[1], w1.u[1]);
                fma2(A2, h.u[1], w2.u[1]); fma2(A3, h.u[1], w3.u[1]);
            }
            U2 r0, r1, r2, r3;
            r0.u = A0; r1.u = A1; r2.u = A2; r3.u = A3;
            if (kh == 1) {
                *(float4*)pp = make_float4(r0.f.x + r0.f.y, r1.f.x + r1.f.y,
                                           r2.f.x + r2.f.y, r3.f.x + r3.f.y);
            }
            __syncthreads();

            float hn = 0.f;
            if (kh == 0) {
                float4 p = *(const float4*)pp;
                float zi = r0.f.x + r0.f.y + p.x + xgB.x;
                float zf = r1.f.x + r1.f.y + p.y + xgB.y;
                float zg = r2.f.x + r2.f.y + p.z + xgB.z;
                float zo = r3.f.x + r3.f.y + p.w + xgB.w;
                float si = 1.f / (1.f + expf(-zi));
                float sf = 1.f / (1.f + expf(-zf));
                float so = 1.f / (1.f + expf(-zo));
                float cn = sf * cregB + si * tanhf(zg);
                hn = so * tanhf(cn);
                cregB = cn;
                __stcg(&g_h[(size_t)(pout * 2 + 1) * 64 * 256 + b * 256 + hu], hn);
            }
            gbar_arrive(ctrB);
            if (kh == 0) {
                out[((size_t)b * Tl + tt) * 512 + 256 + hu] = hn;
                if (t + 1 < Tl)
                    xgB = __ldg((const float4*)&xw_b[((size_t)b * Tl + tt - 1) * 1024 + (hu << 2)]);
            }
        }
    }
    if (kh == 0) {
        g_c[(size_t)(0 * 64 + b) * 256 + hu] = cregF;
        g_c[(size_t)(1 * 64 + b) * 256 + hu] = cregB;
    }
}

// ---------------- persistent decoder (R8-proven) ----------------
#define DEC_SMEM ((16 * 1032 + 64 * 132 + 512 + 128 + 256 + 512 + 64 + 256) * 4)
__global__ __launch_bounds__(256) void dec_scan(
    const float* __restrict__ sWih, const float* __restrict__ sWhh,
    const float* __restrict__ sb, const int* __restrict__ gt,
    const float* __restrict__ phi_b,
    const float* __restrict__ fcW, const float* __restrict__ fcb,
    float* __restrict__ out_lps)
{
    extern __shared__ float smem[];
    float* sh_w  = smem;
    float* sh_x  = sh_w + 16 * 1032;
    float* sh_h  = sh_x + 64 * 132;
    float* sh_q  = sh_h + 512;
    float* sh_e  = sh_q + 128;
    float* sh_c2 = sh_e + 256;
    float* sh_l  = sh_c2 + 512;
    float* sr    = sh_l + 64;

    int tid = threadIdx.x;
    int lane = tid & 31, wrp = tid >> 5;
    int u = wrp & 3, bh = wrp >> 2;
    int b = bh * 32 + lane;
    int hu0 = blockIdx.x << 2;
    int hu = hu0 + u;
    unsigned epoch = 0;
    const unsigned nb = gridDim.x;
    unsigned* ctr = &g_barD;

    for (int i = tid; i < 16 * 256; i += 256) {
        int r = i >> 8, kq = (i & 255) << 2;
        int grow = (r >> 2) * SHID + hu0 + (r & 3);
        float4 v;
        if (kq < 512) v = *(const float4*)&sWih[(size_t)grow * 560 + 48 + kq];
        else          v = *(const float4*)&sWhh[(size_t)grow * 512 + (kq - 512)];
        *(float4*)&sh_w[r * 1032 + kq] = v;
    }

    float creg = 0.f;
    __stcg(&g_dh[(size_t)b * 512 + hu], 0.f);
    __stcg(&g_ctx[(size_t)b * 512 + hu], __ldg(&g_feats[(size_t)b * 256 * 512 + hu]));
    gbar(ctr, epoch, nb);

    float bi0 = sb[0 * SHID + hu], bi1 = sb[1 * SHID + hu];
    float bi2 = sb[2 * SHID + hu], bi3 = sb[3 * SHID + hu];

    for (int t = 0; t < TDEC; t++) {
        int pin = t & 1, pout = pin ^ 1;
        int tok = (t == 0) ? 0 : gt[b * TDEC + (t - 1)];
        U2 A0, A1, A2, A3;
        A0.f = make_float2(sWih[(size_t)(0 * SHID + hu) * 560 + tok] + bi0, 0.f);
        A1.f = make_float2(sWih[(size_t)(1 * SHID + hu) * 560 + tok] + bi1, 0.f);
        A2.f = make_float2(sWih[(size_t)(2 * SHID + hu) * 560 + tok] + bi2, 0.f);
        A3.f = make_float2(sWih[(size_t)(3 * SHID + hu) * 560 + tok] + bi3, 0.f);

        const float* hin = g_dh + (size_t)pin * 64 * 512;
        for (int c = 0; c < 8; c++) {
            __syncthreads();
            const float* src = (c < 4) ? (g_ctx + (c << 7)) : (hin + ((c - 4) << 7));
            for (int i = tid; i < 64 * 32; i += 256) {
                int bb = i >> 5, kq = (i & 31) << 2;
                *(float4*)&sh_x[bb * 132 + kq] = __ldcg((const float4*)&src[(size_t)bb * 512 + kq]);
            }
            __syncthreads();
            const float* wp = sh_w + c * 128;
#pragma unroll 8
            for (int kk = 0; kk < 128; kk += 4) {
                UP h, w0, w1, w2, w3;
                h.f  = *(const float4*)&sh_x[b * 132 + kk];
                w0.f = *(const float4*)&wp[(0 * 4 + u) * 1032 + kk];
                w1.f = *(const float4*)&wp[(1 * 4 + u) * 1032 + kk];
                w2.f = *(const float4*)&wp[(2 * 4 + u) * 1032 + kk];
                w3.f = *(const float4*)&wp[(3 * 4 + u) * 1032 + kk];
                fma2(A0.u, h.u[0], w0.u[0]); fma2(A1.u, h.u[0], w1.u[0]);
                fma2(A2.u, h.u[0], w2.u[0]); fma2(A3.u, h.u[0], w3.u[0]);
                fma2(A0.u, h.u[1], w0.u[1]); fma2(A1.u, h.u[1], w1.u[1]);
                fma2(A2.u, h.u[1], w2.u[1]); fma2(A3.u, h.u[1], w3.u[1]);
            }
        }
        float acc0 = A0.f.x + A0.f.y;
        float acc1 = A1.f.x + A1.f.y;
        float acc2 = A2.f.x + A2.f.y;
        float acc3 = A3.f.x + A3.f.y;
        float si = 1.f / (1.f + expf(-acc0));
        float sf = 1.f / (1.f + expf(-acc1));
        float so = 1.f / (1.f + expf(-acc3));
        float cn = sf * creg + si * tanhf(acc2);
        float hn = so * tanhf(cn);
        creg = cn;
        __stcg(&g_dh[(size_t)pout * 64 * 512 + b * 512 + hu], hn);
        gbar(ctr, epoch, nb);

        if (blockIdx.x < 64) {
            int bb = blockIdx.x;
            const float* h = g_dh + (size_t)pout * 64 * 512 + (size_t)bb * 512;
            for (int i = tid; i < 512; i += 256) sh_h[i] = __ldcg(&h[i]);
            __syncthreads();

            {
                int j = tid >> 1, hf = tid & 1;
                const float* pw = g_phiWt + (size_t)hf * 256 * 128;
                const float* hh = sh_h + hf * 256;
                float a0 = 0.f, a1 = 0.f, a2 = 0.f, a3 = 0.f;
                for (int k = 0; k < 256; k += 4) {
                    a0 += hh[k + 0] * pw[(k + 0) * 128 + j];
                    a1 += hh[k + 1] * pw[(k + 1) * 128 + j];
                    a2 += hh[k + 2] * pw[(k + 2) * 128 + j];
                    a3 += hh[k + 3] * pw[(k + 3) * 128 + j];
                }
                sr[tid] = a0 + a1 + a2 + a3;
            }
            __syncthreads();
            if (tid < 128) {
                float q = sr[2 * tid] + sr[2 * tid + 1] + phi_b[tid];
                sh_q[tid] = q > 0.f ? q : 0.f;
            }
            __syncthreads();

            {
                const float* cfp = g_cf + ((size_t)bb * 256 + tid) * 128;
                float a0 = 0.f, a1 = 0.f, a2 = 0.f, a3 = 0.f;
                for (int j = 0; j < 128; j += 4) {
                    a0 += sh_q[j + 0] * cfp[j + 0];
                    a1 += sh_q[j + 1] * cfp[j + 1];
                    a2 += sh_q[j + 2] * cfp[j + 2];
                    a3 += sh_q[j + 3] * cfp[j + 3];
                }
                sh_e[tid] = a0 + a1 + a2 + a3;
            }
            __syncthreads();

            float v = sh_e[tid];
            sr[tid] = v; __syncthreads();
            for (int s = 128; s > 0; s >>= 1) { if (tid < s) sr[tid] = fmaxf(sr[tid], sr[tid + s]); __syncthreads(); }
            float m = sr[0]; __syncthreads();
            float e = expf(v - m);
            sr[tid] = e; __syncthreads();
            for (int s = 128; s > 0; s >>= 1) { if (tid < s) sr[tid] += sr[tid + s]; __syncthreads(); }
            float inv = 1.f / sr[0];
            __syncthreads();
            sh_e[tid] = e * inv;
            __syncthreads();

            for (int d0 = 0; d0 < 512; d0 += 256) {
                int d = d0 + tid;
                const float* fp = g_feats + (size_t)bb * 256 * 512 + d;
                float a0 = 0.f, a1 = 0.f, a2 = 0.f, a3 = 0.f;
                for (int tt2 = 0; tt2 < 256; tt2 += 4) {
                    a0 += sh_e[tt2 + 0] * fp[(size_t)(tt2 + 0) * 512];
                    a1 += sh_e[tt2 + 1] * fp[(size_t)(tt2 + 1) * 512];
                    a2 += sh_e[tt2 + 2] * fp[(size_t)(tt2 + 2) * 512];
                    a3 += sh_e[tt2 + 3] * fp[(size_t)(tt2 + 3) * 512];
                }
                float cv = a0 + a1 + a2 + a3;
                sh_c2[d] = cv;
                __stcg(&g_ctx[(size_t)bb * 512 + d], cv);
            }
            __syncthreads();

            if (tid < 192) {
                int v2 = tid >> 2, part = tid & 3;
                const float* wr = fcW + (size_t)v2 * 1024 + part * 256;
                const float* src = (part < 2) ? (sh_h + part * 256) : (sh_c2 + (part - 2) * 256);
                float a0 = 0.f, a1 = 0.f, a2 = 0.f, a3 = 0.f;
                for (int k = 0; k < 256; k += 4) {
                    a0 += src[k + 0] * wr[k + 0];
                    a1 += src[k + 1] * wr[k + 1];
                    a2 += src[k + 2] * wr[k + 2];
                    a3 += src[k + 3] * wr[k + 3];
                }
                sr[tid] = a0 + a1 + a2 + a3;
            }
            __syncthreads();
            if (tid < 48) {
                sh_l[tid] = sr[tid * 4] + sr[tid * 4 + 1] + sr[tid * 4 + 2] + sr[tid * 4 + 3] + fcb[tid];
            }
            __syncthreads();
            if (tid < 48) {
                float m2 = -1e30f;
                for (int j = 0; j < 48; j++) m2 = fmaxf(m2, sh_l[j]);
                float s2 = 0.f;
                for (int j = 0; j < 48; j++) s2 += expf(sh_l[j] - m2);
                out_lps[(size_t)bb * TDEC * NVOC + (size_t)t * NVOC + tid] = sh_l[tid] - m2 - logf(s2);
            }
        }
        gbar(ctr, epoch, nb);
    }
}

// ---------------- small helpers ----------------
__global__ void transpose_phi(const float* __restrict__ W) {
    int j = blockIdx.x;
    for (int k = threadIdx.x; k < 512; k += 256) g_phiWt[k * 128 + j] = W[j * 512 + k];
}

__global__ void fin_hc(float* __restrict__ out) {
    int b = blockIdx.x;
    for (int i = threadIdx.x; i < 1024; i += 256) {
        int q = i >> 8, r = i & 255;
        float v;
        if (q == 0)      v = g_h[(size_t)(0 * 2 + 0) * 64 * 256 + b * 256 + r];
        else if (q == 1) v = g_h[(size_t)(0 * 2 + 1) * 64 * 256 + b * 256 + r];
        else if (q == 2) v = g_c[(size_t)(0 * 64 + b) * 256 + r];
        else             v = g_c[(size_t)(1 * 64 + b) * 256 + r];
        out[(size_t)b * 1024 + i] = v;
    }
}

// ---------------- host launcher ----------------
extern "C" void kernel_launch(void* const* d_in, const int* in_sizes, int n_in,
                              void* d_out, int out_size)
{
    const float* inputs = (const float*)d_in[0];
    const int*   gt     = (const int*)d_in[1];
    const float* W[27];
    for (int i = 0; i < 27; i++) W[i] = (const float*)d_in[i + 2];

    float *xw0, *xw1, *out0, *out1, *feats, *cf;
    cudaGetSymbolAddress((void**)&xw0, g_xw0);
    cudaGetSymbolAddress((void**)&xw1, g_xw1);
    cudaGetSymbolAddress((void**)&out0, g_out0);
    cudaGetSymbolAddress((void**)&out1, g_out1);
    cudaGetSymbolAddress((void**)&feats, g_feats);
    cudaGetSymbolAddress((void**)&cf, g_cf);

    cudaFuncSetAttribute(enc_scan, cudaFuncAttributeMaxDynamicSharedMemorySize, ENC_SMEM);
    cudaFuncSetAttribute(dec_scan, cudaFuncAttributeMaxDynamicSharedMemorySize, DEC_SMEM);

    float* dout = (float*)d_out;

    reset_bars<<<1, 32>>>();
    nop_kernel<<<1, 32>>>();
    nop_kernel<<<1, 32>>>();

    // ---------------- encoder ----------------
    const float* A = inputs;
    float* outs[3] = {out0, out1, feats};
    int Tl = 1024, K = 160;
    unsigned ebase = 0;
    for (int l = 0; l < 3; l++) {
        int M = 64 * Tl;
        dim3 gg(1024 / 64, M / 128);
        gemm_bias<<<gg, 256>>>(A, W[l * 6 + 0], W[l * 6 + 2], xw0, M, 1024, K, 0, 1);
        gemm_bias<<<gg, 256>>>(A, W[l * 6 + 3], W[l * 6 + 5], xw1, M, 1024, K, 0, 1);
        enc_scan<<<64, 512, ENC_SMEM>>>(xw0, xw1, W[l * 6 + 1], W[l * 6 + 4],
                                        outs[l], Tl, ebase);
        ebase += 64u * (unsigned)(Tl + 1);
        A = outs[l];
        Tl >>= 1;
        K = 1024;
    }

    // comp_feat = relu(feats @ psi_W^T + psi_b)   [16384,128]
    gemm_bias<<<dim3(2, 16384 / 128), 256>>>(feats, W[23], W[24], cf, 16384, 128, 512, 1, 0);
    transpose_phi<<<128, 256>>>(W[21]);
    fin_hc<<<64, 256>>>(dout + (size_t)BATCH * TDEC * NVOC);

    // ---------------- decoder ----------------
    dec_scan<<<128, 256, DEC_SMEM>>>(W[18], W[19], W[20], gt, W[22], W[25], W[26], dout);
}

// round 13
// speedup vs baseline: 1.3409x; 1.3261x over previous
#include <cuda_runtime.h>
#include <math.h>

// ---------------- problem constants ----------------
#define BATCH 64
#define TDEC  150
#define NVOC  48
#define LHID  256
#define SHID  512
#define NMLP  128

typedef unsigned long long ull;

// ---------------- device scratch ----------------
__device__ float g_xw0[64*1024*1024];
__device__ float g_xw1[64*1024*1024];
__device__ float g_out0[64*1024*512];
__device__ float g_out1[64*512*512];
__device__ float g_feats[64*256*512];
__device__ float g_cf[64*256*128];
__device__ float g_h[2*2*64*256];          // [parity][dir][b][256]
__device__ float g_c[2*64*256];
__device__ float g_dh[2*64*512];
__device__ float g_ctx[64*512];
__device__ float g_phiWt[512*128];
__device__ unsigned g_barE[2];             // per-direction encoder barriers
__device__ unsigned g_barD;                // decoder barrier

// ---------------- split-phase grid barrier (R7/R8-PROVEN primitives) -------
__device__ __forceinline__ void gbar_arrive(unsigned* ctr)
{
    __syncthreads();
    if (threadIdx.x == 0) {
        asm volatile("red.release.gpu.global.add.u32 [%0], %1;"
                     :: "l"(ctr), "r"(1u) : "memory");
    }
}
__device__ __forceinline__ void gbar_wait(unsigned* ctr, unsigned& epoch, unsigned nb)
{
    if (threadIdx.x == 0) {
        unsigned target = epoch + nb;
        unsigned v;
        asm volatile("ld.acquire.gpu.global.u32 %0, [%1];"
                     : "=r"(v) : "l"(ctr) : "memory");
        while (v < target) {
            __nanosleep(64);
            asm volatile("ld.acquire.gpu.global.u32 %0, [%1];"
                         : "=r"(v) : "l"(ctr) : "memory");
        }
    }
    epoch += nb;
    __syncthreads();
}
__device__ __forceinline__ void gbar(unsigned* ctr, unsigned& epoch, unsigned nb)
{
    gbar_arrive(ctr);
    gbar_wait(ctr, epoch, nb);
}

// ---------------- packed fp32x2 FMA (SASS FFMA2) ----------------
__device__ __forceinline__ void fma2(ull& d, ull a, ull b)
{
    asm("fma.rn.f32x2 %0, %1, %2, %0;" : "+l"(d) : "l"(a), "l"(b));
}

union UP { float4 f; ull u[2]; };
union U2 { ull u; float2 f; };

// ---------------- barrier reset ----------------
__global__ void reset_bars() {
    if (threadIdx.x == 0 && blockIdx.x == 0) {
        g_barE[0] = 0; g_barE[1] = 0; g_barD = 0;
    }
}

// ---------------- fp32 GEMM (R2-proven tile): C = A@W^T + bias -------------
// Tile 128(M) x 64(N), BK=16, 256 threads, 8x4 per thread.
// gate_perm: output column n' maps to weight/bias row (n'&3)*256 + (n'>>2).
__global__ __launch_bounds__(256) void gemm_bias(
    const float* __restrict__ A, const float* __restrict__ W,
    const float* __restrict__ bias, float* __restrict__ C,
    int M, int N, int K, int relu, int gate_perm)
{
    __shared__ float As[16 * 132];
    __shared__ float Ws[16 * 68];
    int bm = blockIdx.y << 7, bn = blockIdx.x << 6;
    int tid = threadIdx.x;
    int ty = tid >> 4, tx = tid & 15;
    const float* Ap = A + (size_t)bm * K;

    int wr = tid >> 2, wc = (tid & 3) << 2;
    int nprime = bn + wr;
    int nrow = gate_perm ? ((nprime & 3) * 256 + (nprime >> 2)) : nprime;
    const float* WpRow = W + (size_t)nrow * K;

    float acc[8][4];
#pragma unroll
    for (int i = 0; i < 8; i++)
#pragma unroll
        for (int j = 0; j < 4; j++) acc[i][j] = 0.f;

    for (int k0 = 0; k0 < K; k0 += 16) {
#pragma unroll
        for (int j = 0; j < 2; j++) {
            int idx = tid + 256 * j;
            int r = idx >> 2, c = (idx & 3) << 2;
            float4 v = *(const float4*)&Ap[(size_t)r * K + k0 + c];
            As[(c + 0) * 132 + r] = v.x;
            As[(c + 1) * 132 + r] = v.y;
            As[(c + 2) * 132 + r] = v.z;
            As[(c + 3) * 132 + r] = v.w;
        }
        {
            float4 v = *(const float4*)&WpRow[k0 + wc];
            Ws[(wc + 0) * 68 + wr] = v.x;
            Ws[(wc + 1) * 68 + wr] = v.y;
            Ws[(wc + 2) * 68 + wr] = v.z;
            Ws[(wc + 3) * 68 + wr] = v.w;
        }
        __syncthreads();
#pragma unroll
        for (int kk = 0; kk < 16; kk++) {
            float4 a0 = *(const float4*)&As[kk * 132 + ty * 8];
            float4 a1 = *(const float4*)&As[kk * 132 + ty * 8 + 4];
            float4 w  = *(const float4*)&Ws[kk * 68 + tx * 4];
            acc[0][0] += a0.x * w.x; acc[0][1] += a0.x * w.y; acc[0][2] += a0.x * w.z; acc[0][3] += a0.x * w.w;
            acc[1][0] += a0.y * w.x; acc[1][1] += a0.y * w.y; acc[1][2] += a0.y * w.z; acc[1][3] += a0.y * w.w;
            acc[2][0] += a0.z * w.x; acc[2][1] += a0.z * w.y; acc[2][2] += a0.z * w.z; acc[2][3] += a0.z * w.w;
            acc[3][0] += a0.w * w.x; acc[3][1] += a0.w * w.y; acc[3][2] += a0.w * w.z; acc[3][3] += a0.w * w.w;
            acc[4][0] += a1.x * w.x; acc[4][1] += a1.x * w.y; acc[4][2] += a1.x * w.z; acc[4][3] += a1.x * w.w;
            acc[5][0] += a1.y * w.x; acc[5][1] += a1.y * w.y; acc[5][2] += a1.y * w.z; acc[5][3] += a1.y * w.w;
            acc[6][0] += a1.z * w.x; acc[6][1] += a1.z * w.y; acc[6][2] += a1.z * w.z; acc[6][3] += a1.z * w.w;
            acc[7][0] += a1.w * w.x; acc[7][1] += a1.w * w.y; acc[7][2] += a1.w * w.z; acc[7][3] += a1.w * w.w;
        }
        __syncthreads();
    }
    float bvx, bvy, bvz, bvw;
    if (gate_perm) {
        int n0 = bn + tx * 4;
        bvx = bias[((n0 + 0) & 3) * 256 + ((n0 + 0) >> 2)];
        bvy = bias[((n0 + 1) & 3) * 256 + ((n0 + 1) >> 2)];
        bvz = bias[((n0 + 2) & 3) * 256 + ((n0 + 2) >> 2)];
        bvw = bias[((n0 + 3) & 3) * 256 + ((n0 + 3) >> 2)];
    } else {
        float4 bv = *(const float4*)&bias[bn + tx * 4];
        bvx = bv.x; bvy = bv.y; bvz = bv.z; bvw = bv.w;
    }
#pragma unroll
    for (int i = 0; i < 8; i++) {
        int m = bm + ty * 8 + i;
        float4 o;
        o.x = acc[i][0] + bvx; o.y = acc[i][1] + bvy;
        o.z = acc[i][2] + bvz; o.w = acc[i][3] + bvw;
        if (relu) {
            o.x = fmaxf(o.x, 0.f); o.y = fmaxf(o.y, 0.f);
            o.z = fmaxf(o.z, 0.f); o.w = fmaxf(o.w, 0.f);
        }
        *(float4*)&C[(size_t)m * N + bn + tx * 4] = o;
    }
}

// ---------------- persistent encoder scan: 512 threads, k-split (R8) -------
// warp map: kh = wrp>>3, u = (wrp>>1)&3, bh = wrp&1.
// xw is gate-interleaved: xw[(b*Tl+t)*1024 + hu*4 + gate]
#define ENC_SMEM ((16 * 264 + 64 * 260 + 256 * 4) * 4)
__global__ __launch_bounds__(512) void enc_scan(
    const float* __restrict__ xw_f, const float* __restrict__ xw_b,
    const float* __restrict__ whh_f, const float* __restrict__ whh_b,
    float* __restrict__ out, int Tl, unsigned epoch0)
{
    extern __shared__ float smem[];
    float* sh_w = smem;               // 16 x 256 (pitch 264)
    float* sh_x = smem + 16 * 264;    // 64 x 256 (pitch 260)
    float* sh_p = sh_x + 64 * 260;    // 256 x 4 partials (kh=1 -> kh=0)

    int tid = threadIdx.x;
    int lane = tid & 31, wrp = tid >> 5;
    int kh = wrp >> 3;
    int u = (wrp >> 1) & 3;
    int bh = wrp & 1;
    int b = bh * 32 + lane;
    int dir = blockIdx.y;
    int hu0 = blockIdx.x << 2;
    int hu = hu0 + u;
    unsigned epoch = epoch0;
    const unsigned nb = gridDim.x;       // 64 blocks per direction
    unsigned* ctr = &g_barE[dir];

    const float* xw  = dir ? xw_b  : xw_f;
    const float* Whh = dir ? whh_b : whh_f;

    // resident weights: rows r = gate*4 + unit
    for (int i = tid; i < 16 * 64; i += 512) {
        int r = i >> 6, kq = (i & 63) << 2;
        int grow = ((r >> 2) << 8) + hu0 + (r & 3);
        *(float4*)&sh_w[r * 264 + kq] = *(const float4*)&Whh[(size_t)grow * 256 + kq];
    }

    float creg = 0.f;
    if (kh == 0)
        __stcg(&g_h[(size_t)(0 * 2 + dir) * 64 * 256 + b * 256 + hu], 0.f);
    gbar(ctr, epoch, nb);

    const float* wr0 = &sh_w[(0 * 4 + u) * 264 + kh * 128];
    const float* wr1 = &sh_w[(1 * 4 + u) * 264 + kh * 128];
    const float* wr2 = &sh_w[(2 * 4 + u) * 264 + kh * 128];
    const float* wr3 = &sh_w[(3 * 4 + u) * 264 + kh * 128];
    const float* hp  = &sh_x[b * 260 + kh * 128];
    float* pp = &sh_p[(u * 64 + b) * 4];

    // first-step gate prefetch
    float4 xg = make_float4(0.f, 0.f, 0.f, 0.f);
    if (kh == 0) {
        int tt0 = dir ? (Tl - 1) : 0;
        xg = __ldg((const float4*)&xw[((size_t)b * Tl + tt0) * 1024 + (hu << 2)]);
    }

    for (int t = 0; t < Tl; t++) {
        int tt = dir ? (Tl - 1 - t) : t;
        int pin = t & 1, pout = pin ^ 1;
        const float* hin = g_h + (size_t)(pin * 2 + dir) * 64 * 256;

        // broadcast fill of h (8 float4 per thread)
        for (int i = tid; i < 4096; i += 512) {
            int bb = i >> 6, kq = (i & 63) << 2;
            *(float4*)&sh_x[bb * 260 + kq] = __ldcg((const float4*)&hin[bb * 256 + kq]);
        }
        __syncthreads();

        ull A0 = 0ull, A1 = 0ull, A2 = 0ull, A3 = 0ull;
#pragma unroll 8
        for (int kk = 0; kk < 128; kk += 4) {
            UP h, w0, w1, w2, w3;
            h.f  = *(const float4*)&hp[kk];
            w0.f = *(const float4*)&wr0[kk];
            w1.f = *(const float4*)&wr1[kk];
            w2.f = *(const float4*)&wr2[kk];
            w3.f = *(const float4*)&wr3[kk];
            fma2(A0, h.u[0], w0.u[0]); fma2(A1, h.u[0], w1.u[0]);
            fma2(A2, h.u[0], w2.u[0]); fma2(A3, h.u[0], w3.u[0]);
            fma2(A0, h.u[1], w0.u[1]); fma2(A1, h.u[1], w1.u[1]);
            fma2(A2, h.u[1], w2.u[1]); fma2(A3, h.u[1], w3.u[1]);
        }
        U2 r0, r1, r2, r3;
        r0.u = A0; r1.u = A1; r2.u = A2; r3.u = A3;
        if (kh == 1) {
            *(float4*)pp = make_float4(r0.f.x + r0.f.y, r1.f.x + r1.f.y,
                                       r2.f.x + r2.f.y, r3.f.x + r3.f.y);
        }
        __syncthreads();

        float hn = 0.f;
        if (kh == 0) {
            float4 p = *(const float4*)pp;
            float zi = r0.f.x + r0.f.y + p.x + xg.x;
            float zf = r1.f.x + r1.f.y + p.y + xg.y;
            float zg = r2.f.x + r2.f.y + p.z + xg.z;
            float zo = r3.f.x + r3.f.y + p.w + xg.w;
            float si = 1.f / (1.f + expf(-zi));
            float sf = 1.f / (1.f + expf(-zf));
            float so = 1.f / (1.f + expf(-zo));
            float cn = sf * creg + si * tanhf(zg);
            hn = so * tanhf(cn);
            creg = cn;
            __stcg(&g_h[(size_t)(pout * 2 + dir) * 64 * 256 + b * 256 + hu], hn);
        }

        // arrive: release h store; then hide out-store + next xg gather
        gbar_arrive(ctr);
        if (kh == 0) {
            out[((size_t)b * Tl + tt) * 512 + dir * 256 + hu] = hn;
            if (t + 1 < Tl) {
                int tn = dir ? (Tl - 2 - t) : (t + 1);
                xg = __ldg((const float4*)&xw[((size_t)b * Tl + tn) * 1024 + (hu << 2)]);
            }
        }
        gbar_wait(ctr, epoch, nb);
    }
    if (kh == 0)
        g_c[(size_t)(dir * 64 + b) * 256 + hu] = creg;
}

// ---------------- persistent decoder (R8 + 2-chunk fill) ----------------
#define DEC_SMEM ((16 * 1032 + 64 * 516 + 512 + 128 + 256 + 512 + 64 + 256) * 4)
__global__ __launch_bounds__(256) void dec_scan(
    const float* __restrict__ sWih, const float* __restrict__ sWhh,
    const float* __restrict__ sb, const int* __restrict__ gt,
    const float* __restrict__ phi_b,
    const float* __restrict__ fcW, const float* __restrict__ fcb,
    float* __restrict__ out_lps)
{
    extern __shared__ float smem[];
    float* sh_w  = smem;                  // 16 x 1024 (pitch 1032)
    float* sh_x  = sh_w + 16 * 1032;      // 64 x 512 (pitch 516)
    float* sh_h  = sh_x + 64 * 516;
    float* sh_q  = sh_h + 512;
    float* sh_e  = sh_q + 128;
    float* sh_c2 = sh_e + 256;
    float* sh_l  = sh_c2 + 512;
    float* sr    = sh_l + 64;

    int tid = threadIdx.x;
    int lane = tid & 31, wrp = tid >> 5;
    int u = wrp & 3, bh = wrp >> 2;
    int b = bh * 32 + lane;
    int hu0 = blockIdx.x << 2;
    int hu = hu0 + u;
    unsigned epoch = 0;
    const unsigned nb = gridDim.x;
    unsigned* ctr = &g_barD;

    for (int i = tid; i < 16 * 256; i += 256) {
        int r = i >> 8, kq = (i & 255) << 2;
        int grow = (r >> 2) * SHID + hu0 + (r & 3);
        float4 v;
        if (kq < 512) v = *(const float4*)&sWih[(size_t)grow * 560 + 48 + kq];
        else          v = *(const float4*)&sWhh[(size_t)grow * 512 + (kq - 512)];
        *(float4*)&sh_w[r * 1032 + kq] = v;
    }

    float creg = 0.f;
    __stcg(&g_dh[(size_t)b * 512 + hu], 0.f);
    __stcg(&g_ctx[(size_t)b * 512 + hu], __ldg(&g_feats[(size_t)b * 256 * 512 + hu]));
    gbar(ctr, epoch, nb);

    float bi0 = sb[0 * SHID + hu], bi1 = sb[1 * SHID + hu];
    float bi2 = sb[2 * SHID + hu], bi3 = sb[3 * SHID + hu];

    for (int t = 0; t < TDEC; t++) {
        int pin = t & 1, pout = pin ^ 1;
        int tok = (t == 0) ? 0 : gt[b * TDEC + (t - 1)];
        U2 A0, A1, A2, A3;
        A0.f = make_float2(sWih[(size_t)(0 * SHID + hu) * 560 + tok] + bi0, 0.f);
        A1.f = make_float2(sWih[(size_t)(1 * SHID + hu) * 560 + tok] + bi1, 0.f);
        A2.f = make_float2(sWih[(size_t)(2 * SHID + hu) * 560 + tok] + bi2, 0.f);
        A3.f = make_float2(sWih[(size_t)(3 * SHID + hu) * 560 + tok] + bi3, 0.f);

        const float* hin = g_dh + (size_t)pin * 64 * 512;
#pragma unroll
        for (int c = 0; c < 2; c++) {
            __syncthreads();
            const float* src = (c == 0) ? g_ctx : hin;
            for (int i = tid; i < 64 * 128; i += 256) {
                int bb = i >> 7, kq = (i & 127) << 2;
                *(float4*)&sh_x[bb * 516 + kq] = __ldcg((const float4*)&src[(size_t)bb * 512 + kq]);
            }
            __syncthreads();
            const float* w0p = &sh_w[(0 * 4 + u) * 1032 + c * 512];
            const float* w1p = &sh_w[(1 * 4 + u) * 1032 + c * 512];
            const float* w2p = &sh_w[(2 * 4 + u) * 1032 + c * 512];
            const float* w3p = &sh_w[(3 * 4 + u) * 1032 + c * 512];
            const float* hp  = &sh_x[b * 516];
#pragma unroll 8
            for (int kk = 0; kk < 512; kk += 4) {
                UP h, w0, w1, w2, w3;
                h.f  = *(const float4*)&hp[kk];
                w0.f = *(const float4*)&w0p[kk];
                w1.f = *(const float4*)&w1p[kk];
                w2.f = *(const float4*)&w2p[kk];
                w3.f = *(const float4*)&w3p[kk];
                fma2(A0.u, h.u[0], w0.u[0]); fma2(A1.u, h.u[0], w1.u[0]);
                fma2(A2.u, h.u[0], w2.u[0]); fma2(A3.u, h.u[0], w3.u[0]);
                fma2(A0.u, h.u[1], w0.u[1]); fma2(A1.u, h.u[1], w1.u[1]);
                fma2(A2.u, h.u[1], w2.u[1]); fma2(A3.u, h.u[1], w3.u[1]);
            }
        }
        float acc0 = A0.f.x + A0.f.y;
        float acc1 = A1.f.x + A1.f.y;
        float acc2 = A2.f.x + A2.f.y;
        float acc3 = A3.f.x + A3.f.y;
        float si = 1.f / (1.f + expf(-acc0));
        float sf = 1.f / (1.f + expf(-acc1));
        float so = 1.f / (1.f + expf(-acc3));
        float cn = sf * creg + si * tanhf(acc2);
        float hn = so * tanhf(cn);
        creg = cn;
        __stcg(&g_dh[(size_t)pout * 64 * 512 + b * 512 + hu], hn);
        gbar(ctr, epoch, nb);

        if (blockIdx.x < 64) {
            int bb = blockIdx.x;
            const float* h = g_dh + (size_t)pout * 64 * 512 + (size_t)bb * 512;
            for (int i = tid; i < 512; i += 256) sh_h[i] = __ldcg(&h[i]);
            __syncthreads();

            {
                int j = tid >> 1, hf = tid & 1;
                const float* pw = g_phiWt + (size_t)hf * 256 * 128;
                const float* hh = sh_h + hf * 256;
                float a0 = 0.f, a1 = 0.f, a2 = 0.f, a3 = 0.f;
                for (int k = 0; k < 256; k += 4) {
                    a0 += hh[k + 0] * pw[(k + 0) * 128 + j];
                    a1 += hh[k + 1] * pw[(k + 1) * 128 + j];
                    a2 += hh[k + 2] * pw[(k + 2) * 128 + j];
                    a3 += hh[k + 3] * pw[(k + 3) * 128 + j];
                }
                sr[tid] = a0 + a1 + a2 + a3;
            }
            __syncthreads();
            if (tid < 128) {
                float q = sr[2 * tid] + sr[2 * tid + 1] + phi_b[tid];
                sh_q[tid] = q > 0.f ? q : 0.f;
            }
            __syncthreads();

            {
                const float* cfp = g_cf + ((size_t)bb * 256 + tid) * 128;
                float a0 = 0.f, a1 = 0.f, a2 = 0.f, a3 = 0.f;
                for (int j = 0; j < 128; j += 4) {
                    a0 += sh_q[j + 0] * cfp[j + 0];
                    a1 += sh_q[j + 1] * cfp[j + 1];
                    a2 += sh_q[j + 2] * cfp[j + 2];
                    a3 += sh_q[j + 3] * cfp[j + 3];
                }
                sh_e[tid] = a0 + a1 + a2 + a3;
            }
            __syncthreads();

            float v = sh_e[tid];
            sr[tid] = v; __syncthreads();
            for (int s = 128; s > 0; s >>= 1) { if (tid < s) sr[tid] = fmaxf(sr[tid], sr[tid + s]); __syncthreads(); }
            float m = sr[0]; __syncthreads();
            float e = expf(v - m);
            sr[tid] = e; __syncthreads();
            for (int s = 128; s > 0; s >>= 1) { if (tid < s) sr[tid] += sr[tid + s]; __syncthreads(); }
            float inv = 1.f / sr[0];
            __syncthreads();
            sh_e[tid] = e * inv;
            __syncthreads();

            for (int d0 = 0; d0 < 512; d0 += 256) {
                int d = d0 + tid;
                const float* fp = g_feats + (size_t)bb * 256 * 512 + d;
                float a0 = 0.f, a1 = 0.f, a2 = 0.f, a3 = 0.f;
                for (int tt2 = 0; tt2 < 256; tt2 += 4) {
                    a0 += sh_e[tt2 + 0] * fp[(size_t)(tt2 + 0) * 512];
                    a1 += sh_e[tt2 + 1] * fp[(size_t)(tt2 + 1) * 512];
                    a2 += sh_e[tt2 + 2] * fp[(size_t)(tt2 + 2) * 512];
                    a3 += sh_e[tt2 + 3] * fp[(size_t)(tt2 + 3) * 512];
                }
                float cv = a0 + a1 + a2 + a3;
                sh_c2[d] = cv;
                __stcg(&g_ctx[(size_t)bb * 512 + d], cv);
            }
            __syncthreads();

            if (tid < 192) {
                int v2 = tid >> 2, part = tid & 3;
                const float* wr = fcW + (size_t)v2 * 1024 + part * 256;
                const float* src = (part < 2) ? (sh_h + part * 256) : (sh_c2 + (part - 2) * 256);
                float a0 = 0.f, a1 = 0.f, a2 = 0.f, a3 = 0.f;
                for (int k = 0; k < 256; k += 4) {
                    a0 += src[k + 0] * wr[k + 0];
                    a1 += src[k + 1] * wr[k + 1];
                    a2 += src[k + 2] * wr[k + 2];
                    a3 += src[k + 3] * wr[k + 3];
                }
                sr[tid] = a0 + a1 + a2 + a3;
            }
            __syncthreads();
            if (tid < 48) {
                sh_l[tid] = sr[tid * 4] + sr[tid * 4 + 1] + sr[tid * 4 + 2] + sr[tid * 4 + 3] + fcb[tid];
            }
            __syncthreads();
            if (tid < 48) {
                float m2 = -1e30f;
                for (int j = 0; j < 48; j++) m2 = fmaxf(m2, sh_l[j]);
                float s2 = 0.f;
                for (int j = 0; j < 48; j++) s2 += expf(sh_l[j] - m2);
                out_lps[(size_t)bb * TDEC * NVOC + (size_t)t * NVOC + tid] = sh_l[tid] - m2 - logf(s2);
            }
        }
        gbar(ctr, epoch, nb);
    }
}

// ---------------- small helpers ----------------
__global__ void transpose_phi(const float* __restrict__ W) {
    int j = blockIdx.x;
    for (int k = threadIdx.x; k < 512; k += 256) g_phiWt[k * 128 + j] = W[j * 512 + k];
}

__global__ void fin_hc(float* __restrict__ out) {
    int b = blockIdx.x;
    for (int i = threadIdx.x; i < 1024; i += 256) {
        int q = i >> 8, r = i & 255;
        float v;
        if (q == 0)      v = g_h[(size_t)(0 * 2 + 0) * 64 * 256 + b * 256 + r];
        else if (q == 1) v = g_h[(size_t)(0 * 2 + 1) * 64 * 256 + b * 256 + r];
        else if (q == 2) v = g_c[(size_t)(0 * 64 + b) * 256 + r];
        else             v = g_c[(size_t)(1 * 64 + b) * 256 + r];
        out[(size_t)b * 1024 + i] = v;
    }
}

// ---------------- host launcher ----------------
extern "C" void kernel_launch(void* const* d_in, const int* in_sizes, int n_in,
                              void* d_out, int out_size)
{
    const float* inputs = (const float*)d_in[0];
    const int*   gt     = (const int*)d_in[1];
    const float* W[27];
    for (int i = 0; i < 27; i++) W[i] = (const float*)d_in[i + 2];

    float *xw0, *xw1, *out0, *out1, *feats, *cf;
    cudaGetSymbolAddress((void**)&xw0, g_xw0);
    cudaGetSymbolAddress((void**)&xw1, g_xw1);
    cudaGetSymbolAddress((void**)&out0, g_out0);
    cudaGetSymbolAddress((void**)&out1, g_out1);
    cudaGetSymbolAddress((void**)&feats, g_feats);
    cudaGetSymbolAddress((void**)&cf, g_cf);

    cudaFuncSetAttribute(enc_scan, cudaFuncAttributeMaxDynamicSharedMemorySize, ENC_SMEM);
    cudaFuncSetAttribute(dec_scan, cudaFuncAttributeMaxDynamicSharedMemorySize, DEC_SMEM);

    float* dout = (float*)d_out;

    // Launch order puts layer-0 enc_scan at my launch index 3 (ncu slot 5
    // given the harness's ~2 pre-launches): gemm(0), gemm(1), reset(2), enc(3).
    const float* A = inputs;
    float* outs[3] = {out0, out1, feats};
    int Tl = 1024, K = 160;
    unsigned ebase = 0;
    for (int l = 0; l < 3; l++) {
        int M = 64 * Tl;
        dim3 gg(1024 / 64, M / 128);
        gemm_bias<<<gg, 256>>>(A, W[l * 6 + 0], W[l * 6 + 2], xw0, M, 1024, K, 0, 1);
        gemm_bias<<<gg, 256>>>(A, W[l * 6 + 3], W[l * 6 + 5], xw1, M, 1024, K, 0, 1);
        if (l == 0) reset_bars<<<1, 32>>>();
        enc_scan<<<dim3(64, 2), 512, ENC_SMEM>>>(xw0, xw1, W[l * 6 + 1], W[l * 6 + 4],
                                                 outs[l], Tl, ebase);
        ebase += 64u * (unsigned)(Tl + 1);
        A = outs[l];
        Tl >>= 1;
        K = 1024;
    }

    // comp_feat = relu(feats @ psi_W^T + psi_b)   [16384,128]
    gemm_bias<<<dim3(2, 16384 / 128), 256>>>(feats, W[23], W[24], cf, 16384, 128, 512, 1, 0);
    transpose_phi<<<128, 256>>>(W[21]);
    fin_hc<<<64, 256>>>(dout + (size_t)BATCH * TDEC * NVOC);

    // ---------------- decoder ----------------
    dec_scan<<<128, 256, DEC_SMEM>>>(W[18], W[19], W[20], gt, W[22], W[25], W[26], dout);
}

// round 14
// speedup vs baseline: 1.3657x; 1.0185x over previous
#include <cuda_runtime.h>
#include <math.h>

// ---------------- problem constants ----------------
#define BATCH 64
#define TDEC  150
#define NVOC  48
#define LHID  256
#define SHID  512
#define NMLP  128

typedef unsigned long long ull;

// ---------------- device scratch ----------------
__device__ float g_xw0[64*1024*1024];
__device__ float g_xw1[64*1024*1024];
__device__ float g_out0[64*1024*512];
__device__ float g_out1[64*512*512];
__device__ float g_feats[64*256*512];
__device__ float g_cf[64*256*128];
__device__ float g_h[2*2*64*256];          // [parity][dir][b][256]
__device__ float g_c[2*64*256];
__device__ float g_dh[2*64*512];
__device__ float g_ctx[64*512];
__device__ float g_phiWt[512*128];
__device__ unsigned g_barE[2];             // per-direction encoder barriers
__device__ unsigned g_barD;                // decoder barrier

// ---------------- split-phase grid barrier (proven ld.acquire ordering) ----
__device__ __forceinline__ void gbar_arrive(unsigned* ctr)
{
    __syncthreads();
    if (threadIdx.x == 0) {
        asm volatile("red.release.gpu.global.add.u32 [%0], %1;"
                     :: "l"(ctr), "r"(1u) : "memory");
    }
}
__device__ __forceinline__ void gbar_wait(unsigned* ctr, unsigned& epoch, unsigned nb)
{
    if (threadIdx.x == 0) {
        unsigned target = epoch + nb;
        unsigned v;
        int spins = 0;
        for (;;) {
            asm volatile("ld.acquire.gpu.global.u32 %0, [%1];"
                         : "=r"(v) : "l"(ctr) : "memory");
            if (v >= target) break;
            if (++spins > 4) __nanosleep(64);
        }
    }
    epoch += nb;
    __syncthreads();
}
__device__ __forceinline__ void gbar(unsigned* ctr, unsigned& epoch, unsigned nb)
{
    gbar_arrive(ctr);
    gbar_wait(ctr, epoch, nb);
}

// ---------------- packed fp32x2 FMA (SASS FFMA2) ----------------
__device__ __forceinline__ void fma2(ull& d, ull a, ull b)
{
    asm("fma.rn.f32x2 %0, %1, %2, %0;" : "+l"(d) : "l"(a), "l"(b));
}

union UP { float4 f; ull u[2]; };
union U2 { ull u; float2 f; };

// ---------------- barrier reset ----------------
__global__ void reset_bars() {
    if (threadIdx.x == 0 && blockIdx.x == 0) {
        g_barE[0] = 0; g_barE[1] = 0; g_barD = 0;
    }
}

// ---------------- fp32 GEMM, software-pipelined double buffer --------------
// Tile 128(M) x 64(N), BK=16, 256 threads, 8x4 per thread, ONE sync/tile.
// gate_perm: output column n' maps to weight/bias row (n'&3)*256 + (n'>>2).
__global__ __launch_bounds__(256) void gemm_bias(
    const float* __restrict__ A, const float* __restrict__ W,
    const float* __restrict__ bias, float* __restrict__ C,
    int M, int N, int K, int relu, int gate_perm)
{
    __shared__ float As[2][16 * 132];
    __shared__ float Ws[2][16 * 68];
    int bm = blockIdx.y << 7, bn = blockIdx.x << 6;
    int tid = threadIdx.x;
    int ty = tid >> 4, tx = tid & 15;
    const float* Ap = A + (size_t)bm * K;

    int ar0 = tid >> 2, ac = (tid & 3) << 2;          // A row (first), col
    int ar1 = ar0 + 64;                               // A row (second)
    int nprime = bn + ar0;
    int nrow = gate_perm ? ((nprime & 3) * 256 + (nprime >> 2)) : nprime;
    const float* ApRow0 = Ap + (size_t)ar0 * K;
    const float* ApRow1 = Ap + (size_t)ar1 * K;
    const float* WpRow  = W + (size_t)nrow * K;

    float acc[8][4];
#pragma unroll
    for (int i = 0; i < 8; i++)
#pragma unroll
        for (int j = 0; j < 4; j++) acc[i][j] = 0.f;

    float4 ra0 = *(const float4*)&ApRow0[ac];
    float4 ra1 = *(const float4*)&ApRow1[ac];
    float4 rw  = *(const float4*)&WpRow[ac];
    {
        As[0][(ac + 0) * 132 + ar0] = ra0.x;
        As[0][(ac + 1) * 132 + ar0] = ra0.y;
        As[0][(ac + 2) * 132 + ar0] = ra0.z;
        As[0][(ac + 3) * 132 + ar0] = ra0.w;
        As[0][(ac + 0) * 132 + ar1] = ra1.x;
        As[0][(ac + 1) * 132 + ar1] = ra1.y;
        As[0][(ac + 2) * 132 + ar1] = ra1.z;
        As[0][(ac + 3) * 132 + ar1] = ra1.w;
        Ws[0][(ac + 0) * 68 + ar0] = rw.x;
        Ws[0][(ac + 1) * 68 + ar0] = rw.y;
        Ws[0][(ac + 2) * 68 + ar0] = rw.z;
        Ws[0][(ac + 3) * 68 + ar0] = rw.w;
    }
    __syncthreads();

    int buf = 0;
    for (int k0 = 0; k0 < K; k0 += 16) {
        int more = (k0 + 16 < K);
        if (more) {
            ra0 = *(const float4*)&ApRow0[k0 + 16 + ac];
            ra1 = *(const float4*)&ApRow1[k0 + 16 + ac];
            rw  = *(const float4*)&WpRow[k0 + 16 + ac];
        }
        const float* Ab = As[buf];
        const float* Wb = Ws[buf];
#pragma unroll
        for (int kk = 0; kk < 16; kk++) {
            float4 a0 = *(const float4*)&Ab[kk * 132 + ty * 8];
            float4 a1 = *(const float4*)&Ab[kk * 132 + ty * 8 + 4];
            float4 w  = *(const float4*)&Wb[kk * 68 + tx * 4];
            acc[0][0] += a0.x * w.x; acc[0][1] += a0.x * w.y; acc[0][2] += a0.x * w.z; acc[0][3] += a0.x * w.w;
            acc[1][0] += a0.y * w.x; acc[1][1] += a0.y * w.y; acc[1][2] += a0.y * w.z; acc[1][3] += a0.y * w.w;
            acc[2][0] += a0.z * w.x; acc[2][1] += a0.z * w.y; acc[2][2] += a0.z * w.z; acc[2][3] += a0.z * w.w;
            acc[3][0] += a0.w * w.x; acc[3][1] += a0.w * w.y; acc[3][2] += a0.w * w.z; acc[3][3] += a0.w * w.w;
            acc[4][0] += a1.x * w.x; acc[4][1] += a1.x * w.y; acc[4][2] += a1.x * w.z; acc[4][3] += a1.x * w.w;
            acc[5][0] += a1.y * w.x; acc[5][1] += a1.y * w.y; acc[5][2] += a1.y * w.z; acc[5][3] += a1.y * w.w;
            acc[6][0] += a1.z * w.x; acc[6][1] += a1.z * w.y; acc[6][2] += a1.z * w.z; acc[6][3] += a1.z * w.w;
            acc[7][0] += a1.w * w.x; acc[7][1] += a1.w * w.y; acc[7][2] += a1.w * w.z; acc[7][3] += a1.w * w.w;
        }
        if (more) {
            int nb2 = buf ^ 1;
            As[nb2][(ac + 0) * 132 + ar0] = ra0.x;
            As[nb2][(ac + 1) * 132 + ar0] = ra0.y;
            As[nb2][(ac + 2) * 132 + ar0] = ra0.z;
            As[nb2][(ac + 3) * 132 + ar0] = ra0.w;
            As[nb2][(ac + 0) * 132 + ar1] = ra1.x;
            As[nb2][(ac + 1) * 132 + ar1] = ra1.y;
            As[nb2][(ac + 2) * 132 + ar1] = ra1.z;
            As[nb2][(ac + 3) * 132 + ar1] = ra1.w;
            Ws[nb2][(ac + 0) * 68 + ar0] = rw.x;
            Ws[nb2][(ac + 1) * 68 + ar0] = rw.y;
            Ws[nb2][(ac + 2) * 68 + ar0] = rw.z;
            Ws[nb2][(ac + 3) * 68 + ar0] = rw.w;
            __syncthreads();
            buf = nb2;
        }
    }
    float bvx, bvy, bvz, bvw;
    if (gate_perm) {
        int n0 = bn + tx * 4;
        bvx = bias[((n0 + 0) & 3) * 256 + ((n0 + 0) >> 2)];
        bvy = bias[((n0 + 1) & 3) * 256 + ((n0 + 1) >> 2)];
        bvz = bias[((n0 + 2) & 3) * 256 + ((n0 + 2) >> 2)];
        bvw = bias[((n0 + 3) & 3) * 256 + ((n0 + 3) >> 2)];
    } else {
        float4 bv = *(const float4*)&bias[bn + tx * 4];
        bvx = bv.x; bvy = bv.y; bvz = bv.z; bvw = bv.w;
    }
#pragma unroll
    for (int i = 0; i < 8; i++) {
        int m = bm + ty * 8 + i;
        float4 o;
        o.x = acc[i][0] + bvx; o.y = acc[i][1] + bvy;
        o.z = acc[i][2] + bvz; o.w = acc[i][3] + bvw;
        if (relu) {
            o.x = fmaxf(o.x, 0.f); o.y = fmaxf(o.y, 0.f);
            o.z = fmaxf(o.z, 0.f); o.w = fmaxf(o.w, 0.f);
        }
        *(float4*)&C[(size_t)m * N + bn + tx * 4] = o;
    }
}

// ---------------- persistent encoder scan: 512 threads, k-split (R8) -------
#define ENC_SMEM ((16 * 264 + 64 * 260 + 256 * 4) * 4)
__global__ __launch_bounds__(512) void enc_scan(
    const float* __restrict__ xw_f, const float* __restrict__ xw_b,
    const float* __restrict__ whh_f, const float* __restrict__ whh_b,
    float* __restrict__ out, int Tl, unsigned epoch0)
{
    extern __shared__ float smem[];
    float* sh_w = smem;               // 16 x 256 (pitch 264)
    float* sh_x = smem + 16 * 264;    // 64 x 256 (pitch 260)
    float* sh_p = sh_x + 64 * 260;    // 256 x 4 partials (kh=1 -> kh=0)

    int tid = threadIdx.x;
    int lane = tid & 31, wrp = tid >> 5;
    int kh = wrp >> 3;
    int u = (wrp >> 1) & 3;
    int bh = wrp & 1;
    int b = bh * 32 + lane;
    int dir = blockIdx.y;
    int hu0 = blockIdx.x << 2;
    int hu = hu0 + u;
    unsigned epoch = epoch0;
    const unsigned nb = gridDim.x;
    unsigned* ctr = &g_barE[dir];

    const float* xw  = dir ? xw_b  : xw_f;
    const float* Whh = dir ? whh_b : whh_f;

    for (int i = tid; i < 16 * 64; i += 512) {
        int r = i >> 6, kq = (i & 63) << 2;
        int grow = ((r >> 2) << 8) + hu0 + (r & 3);
        *(float4*)&sh_w[r * 264 + kq] = *(const float4*)&Whh[(size_t)grow * 256 + kq];
    }

    float creg = 0.f;
    if (kh == 0)
        __stcg(&g_h[(size_t)(0 * 2 + dir) * 64 * 256 + b * 256 + hu], 0.f);
    gbar(ctr, epoch, nb);

    const float* wr0 = &sh_w[(0 * 4 + u) * 264 + kh * 128];
    const float* wr1 = &sh_w[(1 * 4 + u) * 264 + kh * 128];
    const float* wr2 = &sh_w[(2 * 4 + u) * 264 + kh * 128];
    const float* wr3 = &sh_w[(3 * 4 + u) * 264 + kh * 128];
    const float* hp  = &sh_x[b * 260 + kh * 128];
    float* pp = &sh_p[(u * 64 + b) * 4];

    float4 xg = make_float4(0.f, 0.f, 0.f, 0.f);
    if (kh == 0) {
        int tt0 = dir ? (Tl - 1) : 0;
        xg = __ldg((const float4*)&xw[((size_t)b * Tl + tt0) * 1024 + (hu << 2)]);
    }

    for (int t = 0; t < Tl; t++) {
        int tt = dir ? (Tl - 1 - t) : t;
        int pin = t & 1, pout = pin ^ 1;
        const float* hin = g_h + (size_t)(pin * 2 + dir) * 64 * 256;

        for (int i = tid; i < 4096; i += 512) {
            int bb = i >> 6, kq = (i & 63) << 2;
            *(float4*)&sh_x[bb * 260 + kq] = __ldcg((const float4*)&hin[bb * 256 + kq]);
        }
        __syncthreads();

        ull A0 = 0ull, A1 = 0ull, A2 = 0ull, A3 = 0ull;
#pragma unroll 8
        for (int kk = 0; kk < 128; kk += 4) {
            UP h, w0, w1, w2, w3;
            h.f  = *(const float4*)&hp[kk];
            w0.f = *(const float4*)&wr0[kk];
            w1.f = *(const float4*)&wr1[kk];
            w2.f = *(const float4*)&wr2[kk];
            w3.f = *(const float4*)&wr3[kk];
            fma2(A0, h.u[0], w0.u[0]); fma2(A1, h.u[0], w1.u[0]);
            fma2(A2, h.u[0], w2.u[0]); fma2(A3, h.u[0], w3.u[0]);
            fma2(A0, h.u[1], w0.u[1]); fma2(A1, h.u[1], w1.u[1]);
            fma2(A2, h.u[1], w2.u[1]); fma2(A3, h.u[1], w3.u[1]);
        }
        U2 r0, r1, r2, r3;
        r0.u = A0; r1.u = A1; r2.u = A2; r3.u = A3;
        if (kh == 1) {
            *(float4*)pp = make_float4(r0.f.x + r0.f.y, r1.f.x + r1.f.y,
                                       r2.f.x + r2.f.y, r3.f.x + r3.f.y);
        }
        __syncthreads();

        float hn = 0.f;
        if (kh == 0) {
            float4 p = *(const float4*)pp;
            float zi = r0.f.x + r0.f.y + p.x + xg.x;
            float zf = r1.f.x + r1.f.y + p.y + xg.y;
            float zg = r2.f.x + r2.f.y + p.z + xg.z;
            float zo = r3.f.x + r3.f.y + p.w + xg.w;
            float si = 1.f / (1.f + expf(-zi));
            float sf = 1.f / (1.f + expf(-zf));
            float so = 1.f / (1.f + expf(-zo));
            float cn = sf * creg + si * tanhf(zg);
            hn = so * tanhf(cn);
            creg = cn;
            __stcg(&g_h[(size_t)(pout * 2 + dir) * 64 * 256 + b * 256 + hu], hn);
        }

        gbar_arrive(ctr);
        if (kh == 0) {
            out[((size_t)b * Tl + tt) * 512 + dir * 256 + hu] = hn;
            if (t + 1 < Tl) {
                int tn = dir ? (Tl - 2 - t) : (t + 1);
                xg = __ldg((const float4*)&xw[((size_t)b * Tl + tn) * 1024 + (hu << 2)]);
            }
        }
        gbar_wait(ctr, epoch, nb);
    }
    if (kh == 0)
        g_c[(size_t)(dir * 64 + b) * 256 + hu] = creg;
}

// ---------------- persistent decoder (R13) ----------------
#define DEC_SMEM ((16 * 1032 + 64 * 516 + 512 + 128 + 256 + 512 + 64 + 256) * 4)
__global__ __launch_bounds__(256) void dec_scan(
    const float* __restrict__ sWih, const float* __restrict__ sWhh,
    const float* __restrict__ sb, const int* __restrict__ gt,
    const float* __restrict__ phi_b,
    const float* __restrict__ fcW, const float* __restrict__ fcb,
    float* __restrict__ out_lps)
{
    extern __shared__ float smem[];
    float* sh_w  = smem;
    float* sh_x  = sh_w + 16 * 1032;
    float* sh_h  = sh_x + 64 * 516;
    float* sh_q  = sh_h + 512;
    float* sh_e  = sh_q + 128;
    float* sh_c2 = sh_e + 256;
    float* sh_l  = sh_c2 + 512;
    float* sr    = sh_l + 64;

    int tid = threadIdx.x;
    int lane = tid & 31, wrp = tid >> 5;
    int u = wrp & 3, bh = wrp >> 2;
    int b = bh * 32 + lane;
    int hu0 = blockIdx.x << 2;
    int hu = hu0 + u;
    unsigned epoch = 0;
    const unsigned nb = gridDim.x;
    unsigned* ctr = &g_barD;

    for (int i = tid; i < 16 * 256; i += 256) {
        int r = i >> 8, kq = (i & 255) << 2;
        int grow = (r >> 2) * SHID + hu0 + (r & 3);
        float4 v;
        if (kq < 512) v = *(const float4*)&sWih[(size_t)grow * 560 + 48 + kq];
        else          v = *(const float4*)&sWhh[(size_t)grow * 512 + (kq - 512)];
        *(float4*)&sh_w[r * 1032 + kq] = v;
    }

    float creg = 0.f;
    __stcg(&g_dh[(size_t)b * 512 + hu], 0.f);
    __stcg(&g_ctx[(size_t)b * 512 + hu], __ldg(&g_feats[(size_t)b * 256 * 512 + hu]));
    gbar(ctr, epoch, nb);

    float bi0 = sb[0 * SHID + hu], bi1 = sb[1 * SHID + hu];
    float bi2 = sb[2 * SHID + hu], bi3 = sb[3 * SHID + hu];

    for (int t = 0; t < TDEC; t++) {
        int pin = t & 1, pout = pin ^ 1;
        int tok = (t == 0) ? 0 : gt[b * TDEC + (t - 1)];
        U2 A0, A1, A2, A3;
        A0.f = make_float2(sWih[(size_t)(0 * SHID + hu) * 560 + tok] + bi0, 0.f);
        A1.f = make_float2(sWih[(size_t)(1 * SHID + hu) * 560 + tok] + bi1, 0.f);
        A2.f = make_float2(sWih[(size_t)(2 * SHID + hu) * 560 + tok] + bi2, 0.f);
        A3.f = make_float2(sWih[(size_t)(3 * SHID + hu) * 560 + tok] + bi3, 0.f);

        const float* hin = g_dh + (size_t)pin * 64 * 512;
#pragma unroll
        for (int c = 0; c < 2; c++) {
            __syncthreads();
            const float* src = (c == 0) ? g_ctx : hin;
            for (int i = tid; i < 64 * 128; i += 256) {
                int bb = i >> 7, kq = (i & 127) << 2;
                *(float4*)&sh_x[bb * 516 + kq] = __ldcg((const float4*)&src[(size_t)bb * 512 + kq]);
            }
            __syncthreads();
            const float* w0p = &sh_w[(0 * 4 + u) * 1032 + c * 512];
            const float* w1p = &sh_w[(1 * 4 + u) * 1032 + c * 512];
            const float* w2p = &sh_w[(2 * 4 + u) * 1032 + c * 512];
            const float* w3p = &sh_w[(3 * 4 + u) * 1032 + c * 512];
            const float* hp  = &sh_x[b * 516];
#pragma unroll 8
            for (int kk = 0; kk < 512; kk += 4) {
                UP h, w0, w1, w2, w3;
                h.f  = *(const float4*)&hp[kk];
                w0.f = *(const float4*)&w0p[kk];
                w1.f = *(const float4*)&w1p[kk];
                w2.f = *(const float4*)&w2p[kk];
                w3.f = *(const float4*)&w3p[kk];
                fma2(A0.u, h.u[0], w0.u[0]); fma2(A1.u, h.u[0], w1.u[0]);
                fma2(A2.u, h.u[0], w2.u[0]); fma2(A3.u, h.u[0], w3.u[0]);
                fma2(A0.u, h.u[1], w0.u[1]); fma2(A1.u, h.u[1], w1.u[1]);
                fma2(A2.u, h.u[1], w2.u[1]); fma2(A3.u, h.u[1], w3.u[1]);
            }
        }
        float acc0 = A0.f.x + A0.f.y;
        float acc1 = A1.f.x + A1.f.y;
        float acc2 = A2.f.x + A2.f.y;
        float acc3 = A3.f.x + A3.f.y;
        float si = 1.f / (1.f + expf(-acc0));
        float sf = 1.f / (1.f + expf(-acc1));
        float so = 1.f / (1.f + expf(-acc3));
        float cn = sf * creg + si * tanhf(acc2);
        float hn = so * tanhf(cn);
        creg = cn;
        __stcg(&g_dh[(size_t)pout * 64 * 512 + b * 512 + hu], hn);
        gbar(ctr, epoch, nb);

        if (blockIdx.x < 64) {
            int bb = blockIdx.x;
            const float* h = g_dh + (size_t)pout * 64 * 512 + (size_t)bb * 512;
            for (int i = tid; i < 512; i += 256) sh_h[i] = __ldcg(&h[i]);
            __syncthreads();

            {
                int j = tid >> 1, hf = tid & 1;
                const float* pw = g_phiWt + (size_t)hf * 256 * 128;
                const float* hh = sh_h + hf * 256;
                float a0 = 0.f, a1 = 0.f, a2 = 0.f, a3 = 0.f;
                for (int k = 0; k < 256; k += 4) {
                    a0 += hh[k + 0] * pw[(k + 0) * 128 + j];
                    a1 += hh[k + 1] * pw[(k + 1) * 128 + j];
                    a2 += hh[k + 2] * pw[(k + 2) * 128 + j];
                    a3 += hh[k + 3] * pw[(k + 3) * 128 + j];
                }
                sr[tid] = a0 + a1 + a2 + a3;
            }
            __syncthreads();
            if (tid < 128) {
                float q = sr[2 * tid] + sr[2 * tid + 1] + phi_b[tid];
                sh_q[tid] = q > 0.f ? q : 0.f;
            }
            __syncthreads();

            {
                const float* cfp = g_cf + ((size_t)bb * 256 + tid) * 128;
                float a0 = 0.f, a1 = 0.f, a2 = 0.f, a3 = 0.f;
                for (int j = 0; j < 128; j += 4) {
                    a0 += sh_q[j + 0] * cfp[j + 0];
                    a1 += sh_q[j + 1] * cfp[j + 1];
                    a2 += sh_q[j + 2] * cfp[j + 2];
                    a3 += sh_q[j + 3] * cfp[j + 3];
                }
                sh_e[tid] = a0 + a1 + a2 + a3;
            }
            __syncthreads();

            float v = sh_e[tid];
            sr[tid] = v; __syncthreads();
            for (int s = 128; s > 0; s >>= 1) { if (tid < s) sr[tid] = fmaxf(sr[tid], sr[tid + s]); __syncthreads(); }
            float m = sr[0]; __syncthreads();
            float e = expf(v - m);
            sr[tid] = e; __syncthreads();
            for (int s = 128; s > 0; s >>= 1) { if (tid < s) sr[tid] += sr[tid + s]; __syncthreads(); }
            float inv = 1.f / sr[0];
            __syncthreads();
            sh_e[tid] = e * inv;
            __syncthreads();

            for (int d0 = 0; d0 < 512; d0 += 256) {
                int d = d0 + tid;
                const float* fp = g_feats + (size_t)bb * 256 * 512 + d;
                float a0 = 0.f, a1 = 0.f, a2 = 0.f, a3 = 0.f;
                for (int tt2 = 0; tt2 < 256; tt2 += 4) {
                    a0 += sh_e[tt2 + 0] * fp[(size_t)(tt2 + 0) * 512];
                    a1 += sh_e[tt2 + 1] * fp[(size_t)(tt2 + 1) * 512];
                    a2 += sh_e[tt2 + 2] * fp[(size_t)(tt2 + 2) * 512];
                    a3 += sh_e[tt2 + 3] * fp[(size_t)(tt2 + 3) * 512];
                }
                float cv = a0 + a1 + a2 + a3;
                sh_c2[d] = cv;
                __stcg(&g_ctx[(size_t)bb * 512 + d], cv);
            }
            __syncthreads();

            if (tid < 192) {
                int v2 = tid >> 2, part = tid & 3;
                const float* wr = fcW + (size_t)v2 * 1024 + part * 256;
                const float* src = (part < 2) ? (sh_h + part * 256) : (sh_c2 + (part - 2) * 256);
                float a0 = 0.f, a1 = 0.f, a2 = 0.f, a3 = 0.f;
                for (int k = 0; k < 256; k += 4) {
                    a0 += src[k + 0] * wr[k + 0];
                    a1 += src[k + 1] * wr[k + 1];
                    a2 += src[k + 2] * wr[k + 2];
                    a3 += src[k + 3] * wr[k + 3];
                }
                sr[tid] = a0 + a1 + a2 + a3;
            }
            __syncthreads();
            if (tid < 48) {
                sh_l[tid] = sr[tid * 4] + sr[tid * 4 + 1] + sr[tid * 4 + 2] + sr[tid * 4 + 3] + fcb[tid];
            }
            __syncthreads();
            if (tid < 48) {
                float m2 = -1e30f;
                for (int j = 0; j < 48; j++) m2 = fmaxf(m2, sh_l[j]);
                float s2 = 0.f;
                for (int j = 0; j < 48; j++) s2 += expf(sh_l[j] - m2);
                out_lps[(size_t)bb * TDEC * NVOC + (size_t)t * NVOC + tid] = sh_l[tid] - m2 - logf(s2);
            }
        }
        gbar(ctr, epoch, nb);
    }
}

// ---------------- small helpers ----------------
__global__ void transpose_phi(const float* __restrict__ W) {
    int j = blockIdx.x;
    for (int k = threadIdx.x; k < 512; k += 256) g_phiWt[k * 128 + j] = W[j * 512 + k];
}

__global__ void fin_hc(float* __restrict__ out) {
    int b = blockIdx.x;
    for (int i = threadIdx.x; i < 1024; i += 256) {
        int q = i >> 8, r = i & 255;
        float v;
        if (q == 0)      v = g_h[(size_t)(0 * 2 + 0) * 64 * 256 + b * 256 + r];
        else if (q == 1) v = g_h[(size_t)(0 * 2 + 1) * 64 * 256 + b * 256 + r];
        else if (q == 2) v = g_c[(size_t)(0 * 64 + b) * 256 + r];
        else             v = g_c[(size_t)(1 * 64 + b) * 256 + r];
        out[(size_t)b * 1024 + i] = v;
    }
}

// ---------------- host launcher ----------------
extern "C" void kernel_launch(void* const* d_in, const int* in_sizes, int n_in,
                              void* d_out, int out_size)
{
    const float* inputs = (const float*)d_in[0];
    const int*   gt     = (const int*)d_in[1];
    const float* W[27];
    for (int i = 0; i < 27; i++) W[i] = (const float*)d_in[i + 2];

    float *xw0, *xw1, *out0, *out1, *feats, *cf;
    cudaGetSymbolAddress((void**)&xw0, g_xw0);
    cudaGetSymbolAddress((void**)&xw1, g_xw1);
    cudaGetSymbolAddress((void**)&out0, g_out0);
    cudaGetSymbolAddress((void**)&out1, g_out1);
    cudaGetSymbolAddress((void**)&feats, g_feats);
    cudaGetSymbolAddress((void**)&cf, g_cf);

    cudaFuncSetAttribute(enc_scan, cudaFuncAttributeMaxDynamicSharedMemorySize, ENC_SMEM);
    cudaFuncSetAttribute(dec_scan, cudaFuncAttributeMaxDynamicSharedMemorySize, DEC_SMEM);

    float* dout = (float*)d_out;

    const float* A = inputs;
    float* outs[3] = {out0, out1, feats};
    int Tl = 1024, K = 160;
    unsigned ebase = 0;
    for (int l = 0; l < 3; l++) {
        int M = 64 * Tl;
        dim3 gg(1024 / 64, M / 128);
        gemm_bias<<<gg, 256>>>(A, W[l * 6 + 0], W[l * 6 + 2], xw0, M, 1024, K, 0, 1);
        gemm_bias<<<gg, 256>>>(A, W[l * 6 + 3], W[l * 6 + 5], xw1, M, 1024, K, 0, 1);
        if (l == 0) reset_bars<<<1, 32>>>();
        enc_scan<<<dim3(64, 2), 512, ENC_SMEM>>>(xw0, xw1, W[l * 6 + 1], W[l * 6 + 4],
                                                 outs[l], Tl, ebase);
        ebase += 64u * (unsigned)(Tl + 1);
        A = outs[l];
        Tl >>= 1;
        K = 1024;
    }

    // comp_feat = relu(feats @ psi_W^T + psi_b)   [16384,128]
    gemm_bias<<<dim3(2, 16384 / 128), 256>>>(feats, W[23], W[24], cf, 16384, 128, 512, 1, 0);
    transpose_phi<<<128, 256>>>(W[21]);
    fin_hc<<<64, 256>>>(dout + (size_t)BATCH * TDEC * NVOC);

    // ---------------- decoder ----------------
    dec_scan<<<128, 256, DEC_SMEM>>>(W[18], W[19], W[20], gt, W[22], W[25], W[26], dout);
}